// round 2
// baseline (speedup 1.0000x reference)
#include <cuda_runtime.h>
#include <math.h>

#define BB 64
#define NNN 1024
#define CCC 256
#define KKK 512
#define NPAIR 128

__device__ float g_F[(size_t)BB * KKK * CCC];
__device__ float g_norm2[BB * KKK];
__device__ float g_cx[BB * KKK];
__device__ float g_cy[BB * KKK];
__device__ float g_cz[BB * KKK];
__device__ int   g_idx[BB * KKK];
__device__ int   g_neff[BB];
__device__ float g_pmin[NPAIR * 4 * KKK];
__device__ int   g_parg[NPAIR * 4 * KKK];
__device__ float g_pdot[NPAIR * 4 * KKK];
__device__ int   g_corr[NPAIR * KKK];
__device__ float g_s[NPAIR * KKK];

// ---- kernel 0: per-batch top-K via bitonic sort on (-attn, idx) ----
__global__ __launch_bounds__(1024) void topk_kernel(
    const float* __restrict__ attn, const int* __restrict__ num_rt,
    const float* __restrict__ cents, const float* __restrict__ sns)
{
    __shared__ float skey[NNN];
    __shared__ int   sidx[NNN];
    const int b = blockIdx.x, tid = threadIdx.x;
    const int nr = num_rt[b];
    skey[tid] = (tid < nr) ? attn[b * NNN + tid] : -1000000000.0f;
    sidx[tid] = tid;
    __syncthreads();
    for (int size = 2; size <= NNN; size <<= 1)
        for (int stride = size >> 1; stride > 0; stride >>= 1) {
            int j = tid ^ stride;
            if (j > tid) {
                float k1 = skey[tid], k2 = skey[j];
                int   i1 = sidx[tid], i2 = sidx[j];
                bool g  = (k1 < k2) || (k1 == k2 && i1 > i2);
                bool dd = ((tid & size) == 0);
                if (g == dd) { skey[tid] = k2; skey[j] = k1; sidx[tid] = i2; sidx[j] = i1; }
            }
            __syncthreads();
        }
    if (tid < KKK) {
        int i = sidx[tid];
        g_idx[b * KKK + tid] = i;
        float sc = sns[b * 4 + 3];
        float cx = cents[(b * NNN + i) * 3 + 0];
        float cy = cents[(b * NNN + i) * 3 + 1];
        float cz = cents[(b * NNN + i) * 3 + 2];
        if (i < nr) {
            cx = cx * sc + sns[b * 4 + 0];
            cy = cy * sc + sns[b * 4 + 1];
            cz = cz * sc + sns[b * 4 + 2];
        }
        g_cx[b * KKK + tid] = cx;
        g_cy[b * KKK + tid] = cy;
        g_cz[b * KKK + tid] = cz;
    }
    if (tid == 0) g_neff[b] = (nr < KKK) ? nr : KKK;
}

// ---- kernel 1: F = gather(rt) @ W_in + b_in ----
__global__ __launch_bounds__(256) void gemmF_kernel(
    const float* __restrict__ rt, const float* __restrict__ Win,
    const float* __restrict__ bin)
{
    __shared__ float As[16][128];
    __shared__ float Bs[16][128];
    const int tid = threadIdx.x;
    const int r0 = blockIdx.y * 128;
    const int c0 = blockIdx.x * 128;
    const int tx = tid & 15, ty = tid >> 4;
    const int lrow = tid >> 1, lc = (tid & 1) * 4;
    const int grow = r0 + lrow;
    const float* arow = rt + ((size_t)(grow >> 9) * NNN + g_idx[grow]) * CCC;

    float acc[8][8];
#pragma unroll
    for (int i = 0; i < 8; i++)
#pragma unroll
        for (int j = 0; j < 8; j++) acc[i][j] = 0.f;

    for (int cN = 0; cN < CCC; cN += 16) {
        float4 a0 = *(const float4*)(arow + cN + lc);
        float4 a1 = *(const float4*)(arow + cN + lc + 8);
        int q0 = tid, q1 = tid + 256;
        float4 b0 = *(const float4*)(Win + (size_t)(cN + (q0 >> 5)) * CCC + c0 + (q0 & 31) * 4);
        float4 b1 = *(const float4*)(Win + (size_t)(cN + (q1 >> 5)) * CCC + c0 + (q1 & 31) * 4);
        __syncthreads();
        As[lc + 0][lrow] = a0.x; As[lc + 1][lrow] = a0.y;
        As[lc + 2][lrow] = a0.z; As[lc + 3][lrow] = a0.w;
        As[lc + 8][lrow] = a1.x; As[lc + 9][lrow] = a1.y;
        As[lc +10][lrow] = a1.z; As[lc +11][lrow] = a1.w;
        *(float4*)&Bs[q0 >> 5][(q0 & 31) * 4] = b0;
        *(float4*)&Bs[q1 >> 5][(q1 & 31) * 4] = b1;
        __syncthreads();
#pragma unroll
        for (int kk = 0; kk < 16; kk++) {
            float ra[8], rb[8];
            *(float4*)&ra[0] = *(const float4*)&As[kk][ty * 8];
            *(float4*)&ra[4] = *(const float4*)&As[kk][ty * 8 + 4];
            *(float4*)&rb[0] = *(const float4*)&Bs[kk][tx * 8];
            *(float4*)&rb[4] = *(const float4*)&Bs[kk][tx * 8 + 4];
#pragma unroll
            for (int i = 0; i < 8; i++)
#pragma unroll
                for (int j = 0; j < 8; j++) acc[i][j] += ra[i] * rb[j];
        }
    }
#pragma unroll
    for (int i = 0; i < 8; i++) {
        float* dst = g_F + (size_t)(r0 + ty * 8 + i) * CCC + c0 + tx * 8;
#pragma unroll
        for (int j = 0; j < 8; j++) dst[j] = acc[i][j] + bin[c0 + tx * 8 + j];
    }
}

// ---- kernel 1b: row norms of F ----
__global__ __launch_bounds__(256) void norm_kernel()
{
    const int row  = blockIdx.x * 8 + (threadIdx.x >> 5);
    const int lane = threadIdx.x & 31;
    const float* f = g_F + (size_t)row * CCC;
    float s = 0.f;
    for (int c = lane; c < CCC; c += 32) { float v = f[c]; s += v * v; }
#pragma unroll
    for (int m = 16; m >= 1; m >>= 1) s += __shfl_xor_sync(0xffffffffu, s, m);
    if (lane == 0) g_norm2[row] = s;
}

// ---- kernel 2: G = F_a F_c^T with fused per-tile argmin ----
__global__ __launch_bounds__(256) void gemmG_kernel(
    const int* __restrict__ anc, const int* __restrict__ pos,
    const int* __restrict__ neg)
{
    __shared__ float As[16][128];
    __shared__ float Bs[16][128];
    const int tid = threadIdx.x;
    const int p = blockIdx.x;
    const int t = p >> 1, n = p & 1;
    const int a = anc[t];
    const int c = n ? neg[t] : pos[t];
    const int r0 = blockIdx.y * 128;
    const int l0 = blockIdx.z * 128;
    const int tx = tid & 15, ty = tid >> 4;
    const int lrow = tid >> 1, lc = (tid & 1) * 4;
    const float* arow = g_F + ((size_t)a * KKK + r0 + lrow) * CCC;
    const float* brow = g_F + ((size_t)c * KKK + l0 + lrow) * CCC;

    float acc[8][8];
#pragma unroll
    for (int i = 0; i < 8; i++)
#pragma unroll
        for (int j = 0; j < 8; j++) acc[i][j] = 0.f;

    for (int cN = 0; cN < CCC; cN += 16) {
        float4 a0 = *(const float4*)(arow + cN + lc);
        float4 a1 = *(const float4*)(arow + cN + lc + 8);
        float4 b0 = *(const float4*)(brow + cN + lc);
        float4 b1 = *(const float4*)(brow + cN + lc + 8);
        __syncthreads();
        As[lc + 0][lrow] = a0.x; As[lc + 1][lrow] = a0.y;
        As[lc + 2][lrow] = a0.z; As[lc + 3][lrow] = a0.w;
        As[lc + 8][lrow] = a1.x; As[lc + 9][lrow] = a1.y;
        As[lc +10][lrow] = a1.z; As[lc +11][lrow] = a1.w;
        Bs[lc + 0][lrow] = b0.x; Bs[lc + 1][lrow] = b0.y;
        Bs[lc + 2][lrow] = b0.z; Bs[lc + 3][lrow] = b0.w;
        Bs[lc + 8][lrow] = b1.x; Bs[lc + 9][lrow] = b1.y;
        Bs[lc +10][lrow] = b1.z; Bs[lc +11][lrow] = b1.w;
        __syncthreads();
#pragma unroll
        for (int kk = 0; kk < 16; kk++) {
            float ra[8], rb[8];
            *(float4*)&ra[0] = *(const float4*)&As[kk][ty * 8];
            *(float4*)&ra[4] = *(const float4*)&As[kk][ty * 8 + 4];
            *(float4*)&rb[0] = *(const float4*)&Bs[kk][tx * 8];
            *(float4*)&rb[4] = *(const float4*)&Bs[kk][tx * 8 + 4];
#pragma unroll
            for (int i = 0; i < 8; i++)
#pragma unroll
                for (int j = 0; j < 8; j++) acc[i][j] += ra[i] * rb[j];
        }
    }

    float nn2j[8];
#pragma unroll
    for (int j = 0; j < 8; j++) nn2j[j] = g_norm2[c * KKK + l0 + tx * 8 + j];

#pragma unroll
    for (int i = 0; i < 8; i++) {
        float bk = 3.4e38f; int bl = 0; float bd = 0.f;
#pragma unroll
        for (int j = 0; j < 8; j++) {
            float key = nn2j[j] - 2.f * acc[i][j];
            if (key < bk) { bk = key; bl = l0 + tx * 8 + j; bd = acc[i][j]; }
        }
#pragma unroll
        for (int m = 8; m >= 1; m >>= 1) {
            float ok = __shfl_xor_sync(0xffffffffu, bk, m);
            int   ol = __shfl_xor_sync(0xffffffffu, bl, m);
            float od = __shfl_xor_sync(0xffffffffu, bd, m);
            if (ok < bk || (ok == bk && ol < bl)) { bk = ok; bl = ol; bd = od; }
        }
        if (tx == 0) {
            int o = (p * 4 + blockIdx.z) * KKK + r0 + ty * 8 + i;
            g_pmin[o] = bk; g_parg[o] = bl; g_pdot[o] = bd;
        }
    }
}

// ---- kernel 2b: reduce l-tiles -> corr, s ----
__global__ __launch_bounds__(512) void corr_kernel(
    const int* __restrict__ anc, const int* __restrict__ pos,
    const int* __restrict__ neg)
{
    const int p = blockIdx.x, k = threadIdx.x;
    const int t = p >> 1, n = p & 1;
    const int a = anc[t];
    const int c = n ? neg[t] : pos[t];
    float bk = g_pmin[p * 4 * KKK + k];
    int   bl = g_parg[p * 4 * KKK + k];
    float bd = g_pdot[p * 4 * KKK + k];
#pragma unroll
    for (int z = 1; z < 4; z++) {
        float ok = g_pmin[(p * 4 + z) * KKK + k];
        if (ok < bk) { bk = ok; bl = g_parg[(p * 4 + z) * KKK + k]; bd = g_pdot[(p * 4 + z) * KKK + k]; }
    }
    float na = sqrtf(g_norm2[a * KKK + k]);
    float nb = sqrtf(g_norm2[c * KKK + bl]);
    g_s[p * KKK + k]    = fmaxf(bd / (na * nb + 1e-8f), 0.f);
    g_corr[p * KKK + k] = bl;
}

// ---- kernel 3: geo bitmask + power iteration + sort + MLP ----
__global__ __launch_bounds__(512) void pair_kernel(
    const int* __restrict__ anc, const int* __restrict__ pos,
    const int* __restrict__ neg,
    const float* __restrict__ W1, const float* __restrict__ b1,
    const float* __restrict__ W2, const float* __restrict__ b2,
    float* __restrict__ out, int out_size)
{
    __shared__ unsigned int smask[KKK * 16];
    __shared__ float bufA[KKK * 3];
    __shared__ float bufB[KKK * 3];
    __shared__ float red[33];

    const int p = blockIdx.x, tid = threadIdx.x;
    const int t = p >> 1, n = p & 1;
    const int a = anc[t];
    const int c = n ? neg[t] : pos[t];
    const int neffa = g_neff[a], neffc = g_neff[c];
    const int wid = tid >> 5, lane = tid & 31;

    bufA[tid]           = g_cx[a * KKK + tid];
    bufA[KKK + tid]     = g_cy[a * KKK + tid];
    bufA[2 * KKK + tid] = g_cz[a * KKK + tid];
    {
        int j = g_corr[p * KKK + tid];
        bufB[tid]           = g_cx[c * KKK + j];
        bufB[KKK + tid]     = g_cy[c * KKK + j];
        bufB[2 * KKK + tid] = g_cz[c * KKK + j];
    }
    float sk = g_s[p * KKK + tid];
    __syncthreads();

    for (int kr = 0; kr < 32; kr++) {
        int k = wid * 32 + kr;
        float akx = bufA[k], aky = bufA[KKK + k], akz = bufA[2 * KKK + k];
        float qkx = bufB[k], qky = bufB[KKK + k], qkz = bufB[2 * KKK + k];
        bool rowvalid = (k < neffa);
#pragma unroll 4
        for (int ch = 0; ch < 16; ch++) {
            int l = ch * 32 + lane;
            float dx = akx - bufA[l], dy = aky - bufA[KKK + l], dz = akz - bufA[2 * KKK + l];
            float dp = sqrtf(dx * dx + dy * dy + dz * dz + 1e-12f);
            float ex = qkx - bufB[l], ey = qky - bufB[KKK + l], ez = qkz - bufB[2 * KKK + l];
            float dq = sqrtf(ex * ex + ey * ey + ez * ez + 1e-12f);
            bool geo = (fabsf(dp - dq) < 0.5f) && rowvalid && (l < neffc) && (l != k);
            unsigned bits = __ballot_sync(0xffffffffu, geo);
            if (lane == 0) smask[k * 16 + ch] = bits;
        }
    }
    __syncthreads();

    float* sm_u = bufA;
    float v = (float)(1.0 / sqrt((double)KKK));
    for (int it = 0; it < 20; it++) {
        sm_u[tid] = sk * v;
        __syncthreads();
        float acc = 0.f;
        const unsigned* mrow = &smask[tid * 16];
#pragma unroll 4
        for (int w = 0; w < 16; w++) {
            unsigned bits = mrow[w];
            const float* up = sm_u + w * 32;
#pragma unroll
            for (int i = 0; i < 32; i++)
                if (bits & (1u << i)) acc += up[i];
        }
        float wv = sk * acc;
        float ss = wv * wv;
#pragma unroll
        for (int m = 16; m >= 1; m >>= 1) ss += __shfl_xor_sync(0xffffffffu, ss, m);
        if (lane == 0) red[wid] = ss;
        __syncthreads();
        if (wid == 0) {
            float x = (lane < 16) ? red[lane] : 0.f;
#pragma unroll
            for (int m = 8; m >= 1; m >>= 1) x += __shfl_xor_sync(0xffffffffu, x, m);
            if (lane == 0) red[32] = sqrtf(x);
        }
        __syncthreads();
        v = wv / (red[32] + 1e-8f);
    }

    float* sv = bufB;
    __syncthreads();
    sv[tid] = v;
    __syncthreads();
    for (int size = 2; size <= KKK; size <<= 1)
        for (int stride = size >> 1; stride > 0; stride >>= 1) {
            int jj = tid ^ stride;
            if (jj > tid) {
                float x1 = sv[tid], x2 = sv[jj];
                bool g  = (x1 < x2);             // descending
                bool dd = ((tid & size) == 0);
                if (g == dd) { sv[tid] = x2; sv[jj] = x1; }
            }
            __syncthreads();
        }

    float hacc = b1[tid];
#pragma unroll 8
    for (int l = 0; l < KKK; l++) hacc += sv[l] * W1[(size_t)l * KKK + tid];
    float h = fmaxf(hacc, 0.f);
    float contrib = h * W2[tid];
#pragma unroll
    for (int m = 16; m >= 1; m >>= 1) contrib += __shfl_xor_sync(0xffffffffu, contrib, m);
    if (lane == 0) red[wid] = contrib;
    __syncthreads();
    if (tid == 0) {
        float x = 0.f;
        for (int w = 0; w < 16; w++) x += red[w];
        float score = 1.f / (1.f + expf(-(x + b2[0])));
        out[p] = score;
        if (NPAIR + p < out_size) out[NPAIR + p] = (n == 0) ? 1.f : 0.f;
    }
}

extern "C" void kernel_launch(void* const* d_in, const int* in_sizes, int n_in,
                              void* d_out, int out_size) {
    const float* rt    = (const float*)d_in[0];
    const float* cents = (const float*)d_in[1];
    const float* attn  = (const float*)d_in[2];
    const float* sns   = (const float*)d_in[3];
    const int*   nrt   = (const int*)d_in[4];
    const int*   anc   = (const int*)d_in[5];
    const int*   pos   = (const int*)d_in[6];
    const int*   neg   = (const int*)d_in[7];
    const float* Win   = (const float*)d_in[8];
    const float* bin   = (const float*)d_in[9];
    const float* W1    = (const float*)d_in[10];
    const float* b1    = (const float*)d_in[11];
    const float* W2    = (const float*)d_in[12];
    const float* b2    = (const float*)d_in[13];
    float* out = (float*)d_out;

    topk_kernel<<<BB, 1024>>>(attn, nrt, cents, sns);
    gemmF_kernel<<<dim3(CCC / 128, BB * KKK / 128), 256>>>(rt, Win, bin);
    norm_kernel<<<BB * KKK / 8, 256>>>();
    gemmG_kernel<<<dim3(NPAIR, 4, 4), 256>>>(anc, pos, neg);
    corr_kernel<<<NPAIR, 512>>>(anc, pos, neg);
    pair_kernel<<<NPAIR, 512>>>(anc, pos, neg, W1, b1, W2, b2, out, out_size);
}

// round 5
// speedup vs baseline: 1.2043x; 1.2043x over previous
#include <cuda_runtime.h>
#include <cuda_bf16.h>
#include <cstdint>
#include <math.h>

#define BB 64
#define NNN 1024
#define CCC 256
#define KKK 512
#define NPAIR 128

__device__ float g_F[(size_t)BB * KKK * CCC];
__device__ __nv_bfloat16 g_Fh[(size_t)BB * KKK * CCC];
__device__ __nv_bfloat16 g_Fl[(size_t)BB * KKK * CCC];
__device__ float g_D[(size_t)NPAIR * KKK * KKK];
__device__ float g_norm2[BB * KKK];
__device__ float g_cx[BB * KKK];
__device__ float g_cy[BB * KKK];
__device__ float g_cz[BB * KKK];
__device__ int   g_idx[BB * KKK];
__device__ int   g_neff[BB];
__device__ int   g_corr[NPAIR * KKK];
__device__ float g_s[NPAIR * KKK];

__device__ __forceinline__ uint32_t smem_u32(const void* p) {
    uint32_t a;
    asm("{ .reg .u64 t; cvta.to.shared.u64 t, %1; cvt.u32.u64 %0, t; }" : "=r"(a) : "l"(p));
    return a;
}

#define LDSM_X4(R0, R1, R2, R3, ADDR) \
    asm volatile("ldmatrix.sync.aligned.m8n8.x4.shared.b16 {%0,%1,%2,%3}, [%4];" \
        : "=r"(R0), "=r"(R1), "=r"(R2), "=r"(R3) : "r"(ADDR))

#define MMA_BF16(D, A, B0, B1) \
    asm volatile("mma.sync.aligned.m16n8k16.row.col.f32.bf16.bf16.f32 " \
        "{%0,%1,%2,%3}, {%4,%5,%6,%7}, {%8,%9}, {%0,%1,%2,%3};" \
        : "+f"((D)[0]), "+f"((D)[1]), "+f"((D)[2]), "+f"((D)[3]) \
        : "r"((A)[0]), "r"((A)[1]), "r"((A)[2]), "r"((A)[3]), "r"(B0), "r"(B1))

// ---- kernel 0: per-batch top-K via bitonic sort on (-attn, idx) ----
__global__ __launch_bounds__(1024) void topk_kernel(
    const float* __restrict__ attn, const int* __restrict__ num_rt,
    const float* __restrict__ cents, const float* __restrict__ sns)
{
    __shared__ float skey[NNN];
    __shared__ int   sidx[NNN];
    const int b = blockIdx.x, tid = threadIdx.x;
    const int nr = num_rt[b];
    skey[tid] = (tid < nr) ? attn[b * NNN + tid] : -1000000000.0f;
    sidx[tid] = tid;
    __syncthreads();
    for (int size = 2; size <= NNN; size <<= 1)
        for (int stride = size >> 1; stride > 0; stride >>= 1) {
            int j = tid ^ stride;
            if (j > tid) {
                float k1 = skey[tid], k2 = skey[j];
                int   i1 = sidx[tid], i2 = sidx[j];
                bool g  = (k1 < k2) || (k1 == k2 && i1 > i2);
                bool dd = ((tid & size) == 0);
                if (g == dd) { skey[tid] = k2; skey[j] = k1; sidx[tid] = i2; sidx[j] = i1; }
            }
            __syncthreads();
        }
    if (tid < KKK) {
        int i = sidx[tid];
        g_idx[b * KKK + tid] = i;
        float sc = sns[b * 4 + 3];
        float cx = cents[(b * NNN + i) * 3 + 0];
        float cy = cents[(b * NNN + i) * 3 + 1];
        float cz = cents[(b * NNN + i) * 3 + 2];
        if (i < nr) {
            cx = cx * sc + sns[b * 4 + 0];
            cy = cy * sc + sns[b * 4 + 1];
            cz = cz * sc + sns[b * 4 + 2];
        }
        g_cx[b * KKK + tid] = cx;
        g_cy[b * KKK + tid] = cy;
        g_cz[b * KKK + tid] = cz;
    }
    if (tid == 0) g_neff[b] = (nr < KKK) ? nr : KKK;
}

// ---- kernel 1: F = gather(rt) @ W_in + b_in (fp32 SIMT) ----
__global__ __launch_bounds__(256) void gemmF_kernel(
    const float* __restrict__ rt, const float* __restrict__ Win,
    const float* __restrict__ bin)
{
    __shared__ float As[16][128];
    __shared__ float Bs[16][128];
    const int tid = threadIdx.x;
    const int r0 = blockIdx.y * 128;
    const int c0 = blockIdx.x * 128;
    const int tx = tid & 15, ty = tid >> 4;
    const int lrow = tid >> 1, lc = (tid & 1) * 4;
    const int grow = r0 + lrow;
    const float* arow = rt + ((size_t)(grow >> 9) * NNN + g_idx[grow]) * CCC;

    float acc[8][8];
#pragma unroll
    for (int i = 0; i < 8; i++)
#pragma unroll
        for (int j = 0; j < 8; j++) acc[i][j] = 0.f;

    for (int cN = 0; cN < CCC; cN += 16) {
        float4 a0 = *(const float4*)(arow + cN + lc);
        float4 a1 = *(const float4*)(arow + cN + lc + 8);
        int q0 = tid, q1 = tid + 256;
        float4 b0 = *(const float4*)(Win + (size_t)(cN + (q0 >> 5)) * CCC + c0 + (q0 & 31) * 4);
        float4 b1 = *(const float4*)(Win + (size_t)(cN + (q1 >> 5)) * CCC + c0 + (q1 & 31) * 4);
        __syncthreads();
        As[lc + 0][lrow] = a0.x; As[lc + 1][lrow] = a0.y;
        As[lc + 2][lrow] = a0.z; As[lc + 3][lrow] = a0.w;
        As[lc + 8][lrow] = a1.x; As[lc + 9][lrow] = a1.y;
        As[lc +10][lrow] = a1.z; As[lc +11][lrow] = a1.w;
        *(float4*)&Bs[q0 >> 5][(q0 & 31) * 4] = b0;
        *(float4*)&Bs[q1 >> 5][(q1 & 31) * 4] = b1;
        __syncthreads();
#pragma unroll
        for (int kk = 0; kk < 16; kk++) {
            float ra[8], rb[8];
            *(float4*)&ra[0] = *(const float4*)&As[kk][ty * 8];
            *(float4*)&ra[4] = *(const float4*)&As[kk][ty * 8 + 4];
            *(float4*)&rb[0] = *(const float4*)&Bs[kk][tx * 8];
            *(float4*)&rb[4] = *(const float4*)&Bs[kk][tx * 8 + 4];
#pragma unroll
            for (int i = 0; i < 8; i++)
#pragma unroll
                for (int j = 0; j < 8; j++) acc[i][j] += ra[i] * rb[j];
        }
    }
#pragma unroll
    for (int i = 0; i < 8; i++) {
        float* dst = g_F + (size_t)(r0 + ty * 8 + i) * CCC + c0 + tx * 8;
#pragma unroll
        for (int j = 0; j < 8; j++) dst[j] = acc[i][j] + bin[c0 + tx * 8 + j];
    }
}

// ---- kernel 1b: split F into bf16 hi/lo + row norms ----
__global__ __launch_bounds__(256) void split_kernel()
{
    const int row  = blockIdx.x * 8 + (threadIdx.x >> 5);
    const int lane = threadIdx.x & 31;
    const float* f = g_F + (size_t)row * CCC;
    __nv_bfloat16* fh = g_Fh + (size_t)row * CCC;
    __nv_bfloat16* fl = g_Fl + (size_t)row * CCC;
    float s = 0.f;
    for (int c = lane; c < CCC; c += 32) {
        float v = f[c];
        s += v * v;
        __nv_bfloat16 h = __float2bfloat16(v);
        fh[c] = h;
        fl[c] = __float2bfloat16(v - __bfloat162float(h));
    }
#pragma unroll
    for (int m = 16; m >= 1; m >>= 1) s += __shfl_xor_sync(0xffffffffu, s, m);
    if (lane == 0) g_norm2[row] = s;
}

// ---- kernel 2: mma.sync bf16-split GEMM 128x128 tile -> g_D dots ----
#define LDA 40
__device__ __forceinline__ void load_tileG(
    __nv_bfloat16* dstA, __nv_bfloat16* dstB,
    const __nv_bfloat16* __restrict__ Asrc, const __nv_bfloat16* __restrict__ Bsrc,
    int arow0, int brow0, int c0, int tid)
{
#pragma unroll
    for (int h = 0; h < 2; h++) {
        int idx = tid + h * 256;
        int row = idx >> 2, q = (idx & 3) * 8;
        *(uint4*)(dstA + row * LDA + q) = *(const uint4*)(Asrc + (size_t)(arow0 + row) * CCC + c0 + q);
        *(uint4*)(dstB + row * LDA + q) = *(const uint4*)(Bsrc + (size_t)(brow0 + row) * CCC + c0 + q);
    }
}

__global__ __launch_bounds__(256) void gemmG_mma_kernel(
    const int* __restrict__ anc, const int* __restrict__ pos,
    const int* __restrict__ neg)
{
    __shared__ __nv_bfloat16 sA[2][128 * LDA];
    __shared__ __nv_bfloat16 sB[2][128 * LDA];
    const int tid = threadIdx.x, lane = tid & 31, wid = tid >> 5;
    const int p = blockIdx.x, mtile = blockIdx.y, ntile = blockIdx.z;
    const int t = p >> 1;
    const int a = anc[t];
    const int c = (p & 1) ? neg[t] : pos[t];
    const int arow0 = a * KKK + mtile * 128;
    const int brow0 = c * KKK + ntile * 128;

    const int m_base = (wid >> 1) * 32;
    const int n_base = (wid & 1) * 64;

    float acc[2][8][4];
#pragma unroll
    for (int mi = 0; mi < 2; mi++)
#pragma unroll
        for (int n8 = 0; n8 < 8; n8++)
#pragma unroll
            for (int r = 0; r < 4; r++) acc[mi][n8][r] = 0.f;

    load_tileG(sA[0], sB[0], g_Fh, g_Fh, arow0, brow0, 0, tid);
    __syncthreads();

    for (int kc = 0; kc < 24; kc++) {
        const int buf = kc & 1;
        if (kc + 1 < 24) {
            const int seg = (kc + 1) >> 3;
            const int c0  = ((kc + 1) & 7) * 32;
            const __nv_bfloat16* Asrc = (seg < 2) ? g_Fh : g_Fl;
            const __nv_bfloat16* Bsrc = (seg == 1) ? g_Fl : g_Fh;
            load_tileG(sA[buf ^ 1], sB[buf ^ 1], Asrc, Bsrc, arow0, brow0, c0, tid);
        }
        const uint32_t sa = smem_u32(&sA[buf][0]);
        const uint32_t sb = smem_u32(&sB[buf][0]);
#pragma unroll
        for (int ks = 0; ks < 2; ks++) {
            const int k0 = ks * 16;
            uint32_t af[2][4];
#pragma unroll
            for (int mi = 0; mi < 2; mi++) {
                uint32_t addr = sa + (uint32_t)(((m_base + mi * 16 + (lane & 15)) * LDA + k0 + (lane >> 4) * 8) << 1);
                LDSM_X4(af[mi][0], af[mi][1], af[mi][2], af[mi][3], addr);
            }
            uint32_t bfr[4][4];
#pragma unroll
            for (int nj = 0; nj < 4; nj++) {
                uint32_t addr = sb + (uint32_t)(((n_base + nj * 16 + (lane & 7) + ((lane >> 4) << 3)) * LDA + k0 + ((lane >> 3) & 1) * 8) << 1);
                LDSM_X4(bfr[nj][0], bfr[nj][1], bfr[nj][2], bfr[nj][3], addr);
            }
#pragma unroll
            for (int mi = 0; mi < 2; mi++)
#pragma unroll
                for (int n8 = 0; n8 < 8; n8++)
                    MMA_BF16(acc[mi][n8], af[mi], bfr[n8 >> 1][(n8 & 1) * 2], bfr[n8 >> 1][(n8 & 1) * 2 + 1]);
        }
        __syncthreads();
    }

    // epilogue: store dots to g_D
#pragma unroll
    for (int mi = 0; mi < 2; mi++)
#pragma unroll
        for (int half = 0; half < 2; half++) {
            int grow = mtile * 128 + m_base + mi * 16 + half * 8 + (lane >> 2);
            float* dst = g_D + ((size_t)p * KKK + grow) * KKK + ntile * 128 + n_base + (lane & 3) * 2;
#pragma unroll
            for (int n8 = 0; n8 < 8; n8++) {
                float2 v = make_float2(acc[mi][n8][half * 2 + 0], acc[mi][n8][half * 2 + 1]);
                *(float2*)(dst + n8 * 8) = v;
            }
        }
}

// ---- kernel 2b: exact argmin refinement -> corr, s ----
#define DELTA 0.05f
__global__ __launch_bounds__(256) void refine_kernel(
    const int* __restrict__ anc, const int* __restrict__ pos,
    const int* __restrict__ neg)
{
    __shared__ float snorm[KKK];
    const int p = blockIdx.x, tid = threadIdx.x;
    const int t = p >> 1;
    const int a = anc[t];
    const int c = (p & 1) ? neg[t] : pos[t];
    const int wid = tid >> 5, lane = tid & 31;
    for (int i = tid; i < KKK; i += 256) snorm[i] = g_norm2[c * KKK + i];
    __syncthreads();

    for (int rr = 0; rr < 4; rr++) {
        const int r = blockIdx.y * 32 + rr * 8 + wid;
        const float* drow = g_D + ((size_t)p * KKK + r) * KKK;
        float key[16];
        float bk = 3.4e38f;
#pragma unroll
        for (int i = 0; i < 16; i++) {
            int col = i * 32 + lane;
            key[i] = snorm[col] - 2.f * drow[col];
            bk = fminf(bk, key[i]);
        }
#pragma unroll
        for (int m = 16; m >= 1; m >>= 1) bk = fminf(bk, __shfl_xor_sync(0xffffffffu, bk, m));
        const float thr = bk + DELTA;

        float bestk = 3.4e38f; int bestc = 0; float bestd = 0.f;
        const float* fa = g_F + ((size_t)a * KKK + r) * CCC;
#pragma unroll 1
        for (int i = 0; i < 16; i++) {
            unsigned m = __ballot_sync(0xffffffffu, key[i] <= thr);
            while (m) {
                int b = __ffs(m) - 1; m &= m - 1;
                int col = i * 32 + b;
                const float* fb = g_F + ((size_t)c * KKK + col) * CCC;
                float sd = 0.f;
#pragma unroll
                for (int j = 0; j < 8; j++) sd += fa[lane * 8 + j] * fb[lane * 8 + j];
#pragma unroll
                for (int mm = 16; mm >= 1; mm >>= 1) sd += __shfl_xor_sync(0xffffffffu, sd, mm);
                float ek = snorm[col] - 2.f * sd;
                if (ek < bestk) { bestk = ek; bestc = col; bestd = sd; }
            }
        }
        if (lane == 0) {
            float na = sqrtf(g_norm2[a * KKK + r]);
            float nb = sqrtf(snorm[bestc]);
            g_s[p * KKK + r]    = fmaxf(bestd / (na * nb + 1e-8f), 0.f);
            g_corr[p * KKK + r] = bestc;
        }
    }
}

// ---- kernel 3: geo bitmask + power iteration + sort + MLP ----
__global__ __launch_bounds__(512) void pair_kernel(
    const int* __restrict__ anc, const int* __restrict__ pos,
    const int* __restrict__ neg,
    const float* __restrict__ W1, const float* __restrict__ b1,
    const float* __restrict__ W2, const float* __restrict__ b2,
    float* __restrict__ out, int out_size)
{
    __shared__ unsigned int smask[KKK * 16];
    __shared__ float bufA[KKK * 3];
    __shared__ float bufB[KKK * 3];
    __shared__ float red[33];

    const int p = blockIdx.x, tid = threadIdx.x;
    const int t = p >> 1, n = p & 1;
    const int a = anc[t];
    const int c = n ? neg[t] : pos[t];
    const int neffa = g_neff[a], neffc = g_neff[c];
    const int wid = tid >> 5, lane = tid & 31;

    bufA[tid]           = g_cx[a * KKK + tid];
    bufA[KKK + tid]     = g_cy[a * KKK + tid];
    bufA[2 * KKK + tid] = g_cz[a * KKK + tid];
    {
        int j = g_corr[p * KKK + tid];
        bufB[tid]           = g_cx[c * KKK + j];
        bufB[KKK + tid]     = g_cy[c * KKK + j];
        bufB[2 * KKK + tid] = g_cz[c * KKK + j];
    }
    float sk = g_s[p * KKK + tid];
    __syncthreads();

    for (int kr = 0; kr < 32; kr++) {
        int k = wid * 32 + kr;
        float akx = bufA[k], aky = bufA[KKK + k], akz = bufA[2 * KKK + k];
        float qkx = bufB[k], qky = bufB[KKK + k], qkz = bufB[2 * KKK + k];
        bool rowvalid = (k < neffa);
#pragma unroll 4
        for (int ch = 0; ch < 16; ch++) {
            int l = ch * 32 + lane;
            float dx = akx - bufA[l], dy = aky - bufA[KKK + l], dz = akz - bufA[2 * KKK + l];
            float dp = sqrtf(dx * dx + dy * dy + dz * dz + 1e-12f);
            float ex = qkx - bufB[l], ey = qky - bufB[KKK + l], ez = qkz - bufB[2 * KKK + l];
            float dq = sqrtf(ex * ex + ey * ey + ez * ez + 1e-12f);
            bool geo = (fabsf(dp - dq) < 0.5f) && rowvalid && (l < neffc) && (l != k);
            unsigned bits = __ballot_sync(0xffffffffu, geo);
            if (lane == 0) smask[k * 16 + ch] = bits;
        }
    }
    __syncthreads();

    float* sm_u = bufA;
    float v = (float)(1.0 / sqrt((double)KKK));
    for (int it = 0; it < 20; it++) {
        sm_u[tid] = sk * v;
        __syncthreads();
        float acc = 0.f;
        const unsigned* mrow = &smask[tid * 16];
#pragma unroll 4
        for (int w = 0; w < 16; w++) {
            unsigned bits = mrow[w];
            const float* up = sm_u + w * 32;
#pragma unroll
            for (int i = 0; i < 32; i++)
                if (bits & (1u << i)) acc += up[i];
        }
        float wv = sk * acc;
        float ss = wv * wv;
#pragma unroll
        for (int m = 16; m >= 1; m >>= 1) ss += __shfl_xor_sync(0xffffffffu, ss, m);
        if (lane == 0) red[wid] = ss;
        __syncthreads();
        if (wid == 0) {
            float x = (lane < 16) ? red[lane] : 0.f;
#pragma unroll
            for (int m = 8; m >= 1; m >>= 1) x += __shfl_xor_sync(0xffffffffu, x, m);
            if (lane == 0) red[32] = sqrtf(x);
        }
        __syncthreads();
        v = wv / (red[32] + 1e-8f);
    }

    float* sv = bufB;
    __syncthreads();
    sv[tid] = v;
    __syncthreads();
    for (int size = 2; size <= KKK; size <<= 1)
        for (int stride = size >> 1; stride > 0; stride >>= 1) {
            int jj = tid ^ stride;
            if (jj > tid) {
                float x1 = sv[tid], x2 = sv[jj];
                bool g  = (x1 < x2);
                bool dd = ((tid & size) == 0);
                if (g == dd) { sv[tid] = x2; sv[jj] = x1; }
            }
            __syncthreads();
        }

    float hacc = b1[tid];
#pragma unroll 8
    for (int l = 0; l < KKK; l++) hacc += sv[l] * W1[(size_t)l * KKK + tid];
    float h = fmaxf(hacc, 0.f);
    float contrib = h * W2[tid];
#pragma unroll
    for (int m = 16; m >= 1; m >>= 1) contrib += __shfl_xor_sync(0xffffffffu, contrib, m);
    if (lane == 0) red[wid] = contrib;
    __syncthreads();
    if (tid == 0) {
        float x = 0.f;
        for (int w = 0; w < 16; w++) x += red[w];
        float score = 1.f / (1.f + expf(-(x + b2[0])));
        out[p] = score;
        if (NPAIR + p < out_size) out[NPAIR + p] = (n == 0) ? 1.f : 0.f;
    }
}

extern "C" void kernel_launch(void* const* d_in, const int* in_sizes, int n_in,
                              void* d_out, int out_size) {
    const float* rt    = (const float*)d_in[0];
    const float* cents = (const float*)d_in[1];
    const float* attn  = (const float*)d_in[2];
    const float* sns   = (const float*)d_in[3];
    const int*   nrt   = (const int*)d_in[4];
    const int*   anc   = (const int*)d_in[5];
    const int*   pos   = (const int*)d_in[6];
    const int*   neg   = (const int*)d_in[7];
    const float* Win   = (const float*)d_in[8];
    const float* bin   = (const float*)d_in[9];
    const float* W1    = (const float*)d_in[10];
    const float* b1    = (const float*)d_in[11];
    const float* W2    = (const float*)d_in[12];
    const float* b2    = (const float*)d_in[13];
    float* out = (float*)d_out;

    topk_kernel<<<BB, 1024>>>(attn, nrt, cents, sns);
    gemmF_kernel<<<dim3(CCC / 128, BB * KKK / 128), 256>>>(rt, Win, bin);
    split_kernel<<<BB * KKK / 8, 256>>>();
    gemmG_mma_kernel<<<dim3(NPAIR, 4, 4), 256>>>(anc, pos, neg);
    refine_kernel<<<dim3(NPAIR, 16), 256>>>(anc, pos, neg);
    pair_kernel<<<NPAIR, 512>>>(anc, pos, neg, W1, b1, W2, b2, out, out_size);
}

// round 6
// speedup vs baseline: 1.5057x; 1.2503x over previous
#include <cuda_runtime.h>
#include <cuda_bf16.h>
#include <cstdint>
#include <math.h>

#define BB 64
#define NNN 1024
#define CCC 256
#define KKK 512
#define NPAIR 128

__device__ float g_F[(size_t)BB * KKK * CCC];
__device__ __nv_bfloat16 g_Fh[(size_t)BB * KKK * CCC];
__device__ __nv_bfloat16 g_Fl[(size_t)BB * KKK * CCC];
__device__ float g_D[(size_t)NPAIR * KKK * KKK];
__device__ float g_norm2[BB * KKK];
__device__ float g_cx[BB * KKK];
__device__ float g_cy[BB * KKK];
__device__ float g_cz[BB * KKK];
__device__ int   g_idx[BB * KKK];
__device__ int   g_neff[BB];
__device__ int   g_corr[NPAIR * KKK];
__device__ float g_s[NPAIR * KKK];

__device__ __forceinline__ uint32_t smem_u32(const void* p) {
    uint32_t a;
    asm("{ .reg .u64 t; cvta.to.shared.u64 t, %1; cvt.u32.u64 %0, t; }" : "=r"(a) : "l"(p));
    return a;
}

#define LDSM_X4(R0, R1, R2, R3, ADDR) \
    asm volatile("ldmatrix.sync.aligned.m8n8.x4.shared.b16 {%0,%1,%2,%3}, [%4];" \
        : "=r"(R0), "=r"(R1), "=r"(R2), "=r"(R3) : "r"(ADDR))

#define MMA_BF16(D, A, B0, B1) \
    asm volatile("mma.sync.aligned.m16n8k16.row.col.f32.bf16.bf16.f32 " \
        "{%0,%1,%2,%3}, {%4,%5,%6,%7}, {%8,%9}, {%0,%1,%2,%3};" \
        : "+f"((D)[0]), "+f"((D)[1]), "+f"((D)[2]), "+f"((D)[3]) \
        : "r"((A)[0]), "r"((A)[1]), "r"((A)[2]), "r"((A)[3]), "r"(B0), "r"(B1))

// ---- kernel 0: per-batch top-K via bitonic sort on (-attn, idx) ----
__global__ __launch_bounds__(1024) void topk_kernel(
    const float* __restrict__ attn, const int* __restrict__ num_rt,
    const float* __restrict__ cents, const float* __restrict__ sns)
{
    __shared__ float skey[NNN];
    __shared__ int   sidx[NNN];
    const int b = blockIdx.x, tid = threadIdx.x;
    const int nr = num_rt[b];
    skey[tid] = (tid < nr) ? attn[b * NNN + tid] : -1000000000.0f;
    sidx[tid] = tid;
    __syncthreads();
    for (int size = 2; size <= NNN; size <<= 1)
        for (int stride = size >> 1; stride > 0; stride >>= 1) {
            int j = tid ^ stride;
            if (j > tid) {
                float k1 = skey[tid], k2 = skey[j];
                int   i1 = sidx[tid], i2 = sidx[j];
                bool g  = (k1 < k2) || (k1 == k2 && i1 > i2);
                bool dd = ((tid & size) == 0);
                if (g == dd) { skey[tid] = k2; skey[j] = k1; sidx[tid] = i2; sidx[j] = i1; }
            }
            __syncthreads();
        }
    if (tid < KKK) {
        int i = sidx[tid];
        g_idx[b * KKK + tid] = i;
        float sc = sns[b * 4 + 3];
        float cx = cents[(b * NNN + i) * 3 + 0];
        float cy = cents[(b * NNN + i) * 3 + 1];
        float cz = cents[(b * NNN + i) * 3 + 2];
        if (i < nr) {
            cx = cx * sc + sns[b * 4 + 0];
            cy = cy * sc + sns[b * 4 + 1];
            cz = cz * sc + sns[b * 4 + 2];
        }
        g_cx[b * KKK + tid] = cx;
        g_cy[b * KKK + tid] = cy;
        g_cz[b * KKK + tid] = cz;
    }
    if (tid == 0) g_neff[b] = (nr < KKK) ? nr : KKK;
}

// ---- kernel 1: F = gather(rt) @ W_in + b_in (fp32 SIMT) ----
__global__ __launch_bounds__(256) void gemmF_kernel(
    const float* __restrict__ rt, const float* __restrict__ Win,
    const float* __restrict__ bin)
{
    __shared__ float As[16][128];
    __shared__ float Bs[16][128];
    const int tid = threadIdx.x;
    const int r0 = blockIdx.y * 128;
    const int c0 = blockIdx.x * 128;
    const int tx = tid & 15, ty = tid >> 4;
    const int lrow = tid >> 1, lc = (tid & 1) * 4;
    const int grow = r0 + lrow;
    const float* arow = rt + ((size_t)(grow >> 9) * NNN + g_idx[grow]) * CCC;

    float acc[8][8];
#pragma unroll
    for (int i = 0; i < 8; i++)
#pragma unroll
        for (int j = 0; j < 8; j++) acc[i][j] = 0.f;

    for (int cN = 0; cN < CCC; cN += 16) {
        float4 a0 = *(const float4*)(arow + cN + lc);
        float4 a1 = *(const float4*)(arow + cN + lc + 8);
        int q0 = tid, q1 = tid + 256;
        float4 b0 = *(const float4*)(Win + (size_t)(cN + (q0 >> 5)) * CCC + c0 + (q0 & 31) * 4);
        float4 b1 = *(const float4*)(Win + (size_t)(cN + (q1 >> 5)) * CCC + c0 + (q1 & 31) * 4);
        __syncthreads();
        As[lc + 0][lrow] = a0.x; As[lc + 1][lrow] = a0.y;
        As[lc + 2][lrow] = a0.z; As[lc + 3][lrow] = a0.w;
        As[lc + 8][lrow] = a1.x; As[lc + 9][lrow] = a1.y;
        As[lc +10][lrow] = a1.z; As[lc +11][lrow] = a1.w;
        *(float4*)&Bs[q0 >> 5][(q0 & 31) * 4] = b0;
        *(float4*)&Bs[q1 >> 5][(q1 & 31) * 4] = b1;
        __syncthreads();
#pragma unroll
        for (int kk = 0; kk < 16; kk++) {
            float ra[8], rb[8];
            *(float4*)&ra[0] = *(const float4*)&As[kk][ty * 8];
            *(float4*)&ra[4] = *(const float4*)&As[kk][ty * 8 + 4];
            *(float4*)&rb[0] = *(const float4*)&Bs[kk][tx * 8];
            *(float4*)&rb[4] = *(const float4*)&Bs[kk][tx * 8 + 4];
#pragma unroll
            for (int i = 0; i < 8; i++)
#pragma unroll
                for (int j = 0; j < 8; j++) acc[i][j] += ra[i] * rb[j];
        }
    }
#pragma unroll
    for (int i = 0; i < 8; i++) {
        float* dst = g_F + (size_t)(r0 + ty * 8 + i) * CCC + c0 + tx * 8;
#pragma unroll
        for (int j = 0; j < 8; j++) dst[j] = acc[i][j] + bin[c0 + tx * 8 + j];
    }
}

// ---- kernel 1b: split F into bf16 hi/lo + row norms ----
__global__ __launch_bounds__(256) void split_kernel()
{
    const int row  = blockIdx.x * 8 + (threadIdx.x >> 5);
    const int lane = threadIdx.x & 31;
    const float* f = g_F + (size_t)row * CCC;
    __nv_bfloat16* fh = g_Fh + (size_t)row * CCC;
    __nv_bfloat16* fl = g_Fl + (size_t)row * CCC;
    float s = 0.f;
    for (int c = lane; c < CCC; c += 32) {
        float v = f[c];
        s += v * v;
        __nv_bfloat16 h = __float2bfloat16(v);
        fh[c] = h;
        fl[c] = __float2bfloat16(v - __bfloat162float(h));
    }
#pragma unroll
    for (int m = 16; m >= 1; m >>= 1) s += __shfl_xor_sync(0xffffffffu, s, m);
    if (lane == 0) g_norm2[row] = s;
}

// ---- kernel 2: mma.sync 2-pass bf16-split GEMM 128x128 tile -> g_D dots ----
#define LDA 40
__device__ __forceinline__ void load_tileG(
    __nv_bfloat16* dstA, __nv_bfloat16* dstB,
    const __nv_bfloat16* __restrict__ Asrc, const __nv_bfloat16* __restrict__ Bsrc,
    int arow0, int brow0, int c0, int tid)
{
#pragma unroll
    for (int h = 0; h < 2; h++) {
        int idx = tid + h * 256;
        int row = idx >> 2, q = (idx & 3) * 8;
        *(uint4*)(dstA + row * LDA + q) = *(const uint4*)(Asrc + (size_t)(arow0 + row) * CCC + c0 + q);
        *(uint4*)(dstB + row * LDA + q) = *(const uint4*)(Bsrc + (size_t)(brow0 + row) * CCC + c0 + q);
    }
}

__global__ __launch_bounds__(256) void gemmG_mma_kernel(
    const int* __restrict__ anc, const int* __restrict__ pos,
    const int* __restrict__ neg)
{
    __shared__ __nv_bfloat16 sA[2][128 * LDA];
    __shared__ __nv_bfloat16 sB[2][128 * LDA];
    const int tid = threadIdx.x, lane = tid & 31, wid = tid >> 5;
    const int p = blockIdx.x, mtile = blockIdx.y, ntile = blockIdx.z;
    const int t = p >> 1;
    const int a = anc[t];
    const int c = (p & 1) ? neg[t] : pos[t];
    const int arow0 = a * KKK + mtile * 128;
    const int brow0 = c * KKK + ntile * 128;

    const int m_base = (wid >> 1) * 32;
    const int n_base = (wid & 1) * 64;

    float acc[2][8][4];
#pragma unroll
    for (int mi = 0; mi < 2; mi++)
#pragma unroll
        for (int n8 = 0; n8 < 8; n8++)
#pragma unroll
            for (int r = 0; r < 4; r++) acc[mi][n8][r] = 0.f;

    load_tileG(sA[0], sB[0], g_Fh, g_Fh, arow0, brow0, 0, tid);
    __syncthreads();

    // 2-pass split: seg 0 = A_hi*B_hi, seg 1 = A_lo*B_hi  (dropped A_hi*B_lo
    // bounded by DELTA/2 and fixed up exactly in refine_kernel)
    for (int kc = 0; kc < 16; kc++) {
        const int buf = kc & 1;
        if (kc + 1 < 16) {
            const int seg = (kc + 1) >> 3;
            const int c0  = ((kc + 1) & 7) * 32;
            const __nv_bfloat16* Asrc = seg ? g_Fl : g_Fh;
            load_tileG(sA[buf ^ 1], sB[buf ^ 1], Asrc, g_Fh, arow0, brow0, c0, tid);
        }
        const uint32_t sa = smem_u32(&sA[buf][0]);
        const uint32_t sb = smem_u32(&sB[buf][0]);
#pragma unroll
        for (int ks = 0; ks < 2; ks++) {
            const int k0 = ks * 16;
            uint32_t af[2][4];
#pragma unroll
            for (int mi = 0; mi < 2; mi++) {
                uint32_t addr = sa + (uint32_t)(((m_base + mi * 16 + (lane & 15)) * LDA + k0 + (lane >> 4) * 8) << 1);
                LDSM_X4(af[mi][0], af[mi][1], af[mi][2], af[mi][3], addr);
            }
            uint32_t bfr[4][4];
#pragma unroll
            for (int nj = 0; nj < 4; nj++) {
                uint32_t addr = sb + (uint32_t)(((n_base + nj * 16 + (lane & 7) + ((lane >> 4) << 3)) * LDA + k0 + ((lane >> 3) & 1) * 8) << 1);
                LDSM_X4(bfr[nj][0], bfr[nj][1], bfr[nj][2], bfr[nj][3], addr);
            }
#pragma unroll
            for (int mi = 0; mi < 2; mi++)
#pragma unroll
                for (int n8 = 0; n8 < 8; n8++)
                    MMA_BF16(acc[mi][n8], af[mi], bfr[n8 >> 1][(n8 & 1) * 2], bfr[n8 >> 1][(n8 & 1) * 2 + 1]);
        }
        __syncthreads();
    }

    // epilogue: store dots to g_D
#pragma unroll
    for (int mi = 0; mi < 2; mi++)
#pragma unroll
        for (int half = 0; half < 2; half++) {
            int grow = mtile * 128 + m_base + mi * 16 + half * 8 + (lane >> 2);
            float* dst = g_D + ((size_t)p * KKK + grow) * KKK + ntile * 128 + n_base + (lane & 3) * 2;
#pragma unroll
            for (int n8 = 0; n8 < 8; n8++) {
                float2 v = make_float2(acc[mi][n8][half * 2 + 0], acc[mi][n8][half * 2 + 1]);
                *(float2*)(dst + n8 * 8) = v;
            }
        }
}

// ---- kernel 2b: exact argmin refinement -> corr, s ----
#define DELTA 2.0f
__global__ __launch_bounds__(256) void refine_kernel(
    const int* __restrict__ anc, const int* __restrict__ pos,
    const int* __restrict__ neg)
{
    __shared__ float snorm[KKK];
    const int p = blockIdx.x, tid = threadIdx.x;
    const int t = p >> 1;
    const int a = anc[t];
    const int c = (p & 1) ? neg[t] : pos[t];
    const int wid = tid >> 5, lane = tid & 31;
    for (int i = tid; i < KKK; i += 256) snorm[i] = g_norm2[c * KKK + i];
    __syncthreads();

    for (int rr = 0; rr < 4; rr++) {
        const int r = blockIdx.y * 32 + rr * 8 + wid;
        const float* drow = g_D + ((size_t)p * KKK + r) * KKK;
        float key[16];
        float bk = 3.4e38f;
#pragma unroll
        for (int i = 0; i < 16; i++) {
            int col = i * 32 + lane;
            key[i] = snorm[col] - 2.f * drow[col];
            bk = fminf(bk, key[i]);
        }
#pragma unroll
        for (int m = 16; m >= 1; m >>= 1) bk = fminf(bk, __shfl_xor_sync(0xffffffffu, bk, m));
        const float thr = bk + DELTA;

        float bestk = 3.4e38f; int bestc = 0; float bestd = 0.f;
        const float* fa = g_F + ((size_t)a * KKK + r) * CCC;
#pragma unroll 1
        for (int i = 0; i < 16; i++) {
            unsigned m = __ballot_sync(0xffffffffu, key[i] <= thr);
            while (m) {
                int b = __ffs(m) - 1; m &= m - 1;
                int col = i * 32 + b;
                const float* fb = g_F + ((size_t)c * KKK + col) * CCC;
                float sd = 0.f;
#pragma unroll
                for (int j = 0; j < 8; j++) sd += fa[lane * 8 + j] * fb[lane * 8 + j];
#pragma unroll
                for (int mm = 16; mm >= 1; mm >>= 1) sd += __shfl_xor_sync(0xffffffffu, sd, mm);
                float ek = snorm[col] - 2.f * sd;
                if (ek < bestk) { bestk = ek; bestc = col; bestd = sd; }
            }
        }
        if (lane == 0) {
            float na = sqrtf(g_norm2[a * KKK + r]);
            float nb = sqrtf(snorm[bestc]);
            g_s[p * KKK + r]    = fmaxf(bestd / (na * nb + 1e-8f), 0.f);
            g_corr[p * KKK + r] = bestc;
        }
    }
}

// ---- kernel 3: geo bitmask + power iteration + sort + MLP ----
__global__ __launch_bounds__(512) void pair_kernel(
    const int* __restrict__ anc, const int* __restrict__ pos,
    const int* __restrict__ neg,
    const float* __restrict__ W1, const float* __restrict__ b1,
    const float* __restrict__ W2, const float* __restrict__ b2,
    float* __restrict__ out, int out_size)
{
    __shared__ unsigned int smask[KKK * 16];
    __shared__ float bufA[KKK * 3];
    __shared__ float bufB[KKK * 3];
    __shared__ float red[33];

    const int p = blockIdx.x, tid = threadIdx.x;
    const int t = p >> 1, n = p & 1;
    const int a = anc[t];
    const int c = n ? neg[t] : pos[t];
    const int neffa = g_neff[a], neffc = g_neff[c];
    const int wid = tid >> 5, lane = tid & 31;

    bufA[tid]           = g_cx[a * KKK + tid];
    bufA[KKK + tid]     = g_cy[a * KKK + tid];
    bufA[2 * KKK + tid] = g_cz[a * KKK + tid];
    {
        int j = g_corr[p * KKK + tid];
        bufB[tid]           = g_cx[c * KKK + j];
        bufB[KKK + tid]     = g_cy[c * KKK + j];
        bufB[2 * KKK + tid] = g_cz[c * KKK + j];
    }
    float sk = g_s[p * KKK + tid];
    __syncthreads();

    for (int kr = 0; kr < 32; kr++) {
        int k = wid * 32 + kr;
        float akx = bufA[k], aky = bufA[KKK + k], akz = bufA[2 * KKK + k];
        float qkx = bufB[k], qky = bufB[KKK + k], qkz = bufB[2 * KKK + k];
        bool rowvalid = (k < neffa);
#pragma unroll 4
        for (int ch = 0; ch < 16; ch++) {
            int l = ch * 32 + lane;
            float dx = akx - bufA[l], dy = aky - bufA[KKK + l], dz = akz - bufA[2 * KKK + l];
            float dp = sqrtf(dx * dx + dy * dy + dz * dz + 1e-12f);
            float ex = qkx - bufB[l], ey = qky - bufB[KKK + l], ez = qkz - bufB[2 * KKK + l];
            float dq = sqrtf(ex * ex + ey * ey + ez * ez + 1e-12f);
            bool geo = (fabsf(dp - dq) < 0.5f) && rowvalid && (l < neffc) && (l != k);
            unsigned bits = __ballot_sync(0xffffffffu, geo);
            if (lane == 0) smask[k * 16 + ch] = bits;
        }
    }
    __syncthreads();

    float* sm_u = bufA;
    float v = (float)(1.0 / sqrt((double)KKK));
    for (int it = 0; it < 20; it++) {
        sm_u[tid] = sk * v;
        __syncthreads();
        float acc = 0.f;
        const unsigned* mrow = &smask[tid * 16];
        const float4* u4 = (const float4*)sm_u;
#pragma unroll 4
        for (int w = 0; w < 16; w++) {
            unsigned bits = mrow[w];
#pragma unroll
            for (int q = 0; q < 8; q++) {
                float4 u = u4[w * 8 + q];
                if (bits & (1u << (q * 4 + 0))) acc += u.x;
                if (bits & (1u << (q * 4 + 1))) acc += u.y;
                if (bits & (1u << (q * 4 + 2))) acc += u.z;
                if (bits & (1u << (q * 4 + 3))) acc += u.w;
            }
        }
        float wv = sk * acc;
        float ss = wv * wv;
#pragma unroll
        for (int m = 16; m >= 1; m >>= 1) ss += __shfl_xor_sync(0xffffffffu, ss, m);
        if (lane == 0) red[wid] = ss;
        __syncthreads();
        if (wid == 0) {
            float x = (lane < 16) ? red[lane] : 0.f;
#pragma unroll
            for (int m = 8; m >= 1; m >>= 1) x += __shfl_xor_sync(0xffffffffu, x, m);
            if (lane == 0) red[32] = sqrtf(x);
        }
        __syncthreads();
        v = wv / (red[32] + 1e-8f);
    }

    float* sv = bufB;
    __syncthreads();
    sv[tid] = v;
    __syncthreads();
    for (int size = 2; size <= KKK; size <<= 1)
        for (int stride = size >> 1; stride > 0; stride >>= 1) {
            int jj = tid ^ stride;
            if (jj > tid) {
                float x1 = sv[tid], x2 = sv[jj];
                bool g  = (x1 < x2);
                bool dd = ((tid & size) == 0);
                if (g == dd) { sv[tid] = x2; sv[jj] = x1; }
            }
            __syncthreads();
        }

    float hacc = b1[tid];
    {
        const float4* sv4 = (const float4*)sv;
#pragma unroll 4
        for (int l4 = 0; l4 < 128; l4++) {
            float4 e = sv4[l4];
            hacc += e.x * W1[(size_t)(l4 * 4 + 0) * KKK + tid];
            hacc += e.y * W1[(size_t)(l4 * 4 + 1) * KKK + tid];
            hacc += e.z * W1[(size_t)(l4 * 4 + 2) * KKK + tid];
            hacc += e.w * W1[(size_t)(l4 * 4 + 3) * KKK + tid];
        }
    }
    float h = fmaxf(hacc, 0.f);
    float contrib = h * W2[tid];
#pragma unroll
    for (int m = 16; m >= 1; m >>= 1) contrib += __shfl_xor_sync(0xffffffffu, contrib, m);
    if (lane == 0) red[wid] = contrib;
    __syncthreads();
    if (tid == 0) {
        float x = 0.f;
        for (int w = 0; w < 16; w++) x += red[w];
        float score = 1.f / (1.f + expf(-(x + b2[0])));
        out[p] = score;
        if (NPAIR + p < out_size) out[NPAIR + p] = (n == 0) ? 1.f : 0.f;
    }
}

extern "C" void kernel_launch(void* const* d_in, const int* in_sizes, int n_in,
                              void* d_out, int out_size) {
    const float* rt    = (const float*)d_in[0];
    const float* cents = (const float*)d_in[1];
    const float* attn  = (const float*)d_in[2];
    const float* sns   = (const float*)d_in[3];
    const int*   nrt   = (const int*)d_in[4];
    const int*   anc   = (const int*)d_in[5];
    const int*   pos   = (const int*)d_in[6];
    const int*   neg   = (const int*)d_in[7];
    const float* Win   = (const float*)d_in[8];
    const float* bin   = (const float*)d_in[9];
    const float* W1    = (const float*)d_in[10];
    const float* b1    = (const float*)d_in[11];
    const float* W2    = (const float*)d_in[12];
    const float* b2    = (const float*)d_in[13];
    float* out = (float*)d_out;

    topk_kernel<<<BB, 1024>>>(attn, nrt, cents, sns);
    gemmF_kernel<<<dim3(CCC / 128, BB * KKK / 128), 256>>>(rt, Win, bin);
    split_kernel<<<BB * KKK / 8, 256>>>();
    gemmG_mma_kernel<<<dim3(NPAIR, 4, 4), 256>>>(anc, pos, neg);
    refine_kernel<<<dim3(NPAIR, 16), 256>>>(anc, pos, neg);
    pair_kernel<<<NPAIR, 512>>>(anc, pos, neg, W1, b1, W2, b2, out, out_size);
}

// round 7
// speedup vs baseline: 1.5868x; 1.0538x over previous
#include <cuda_runtime.h>
#include <cuda_bf16.h>
#include <cstdint>
#include <math.h>

#define BB 64
#define NNN 1024
#define CCC 256
#define KKK 512
#define NPAIR 128

__device__ float g_F[(size_t)BB * KKK * CCC];
__device__ __nv_bfloat16 g_Fh[(size_t)BB * KKK * CCC];
__device__ __nv_bfloat16 g_Fl[(size_t)BB * KKK * CCC];
__device__ float g_D[(size_t)NPAIR * KKK * KKK];
__device__ float g_norm2[BB * KKK];
__device__ float g_cx[BB * KKK];
__device__ float g_cy[BB * KKK];
__device__ float g_cz[BB * KKK];
__device__ int   g_idx[BB * KKK];
__device__ int   g_neff[BB];
__device__ int   g_corr[NPAIR * KKK];
__device__ float g_s[NPAIR * KKK];

__device__ __forceinline__ uint32_t smem_u32(const void* p) {
    uint32_t a;
    asm("{ .reg .u64 t; cvta.to.shared.u64 t, %1; cvt.u32.u64 %0, t; }" : "=r"(a) : "l"(p));
    return a;
}
__device__ __forceinline__ void cp_async16(uint32_t saddr, const void* g) {
    asm volatile("cp.async.cg.shared.global [%0], [%1], 16;" :: "r"(saddr), "l"(g));
}
#define CP_COMMIT() asm volatile("cp.async.commit_group;" ::: "memory")

#define LDSM_X4(R0, R1, R2, R3, ADDR) \
    asm volatile("ldmatrix.sync.aligned.m8n8.x4.shared.b16 {%0,%1,%2,%3}, [%4];" \
        : "=r"(R0), "=r"(R1), "=r"(R2), "=r"(R3) : "r"(ADDR))

#define MMA_BF16(D, A, B0, B1) \
    asm volatile("mma.sync.aligned.m16n8k16.row.col.f32.bf16.bf16.f32 " \
        "{%0,%1,%2,%3}, {%4,%5,%6,%7}, {%8,%9}, {%0,%1,%2,%3};" \
        : "+f"((D)[0]), "+f"((D)[1]), "+f"((D)[2]), "+f"((D)[3]) \
        : "r"((A)[0]), "r"((A)[1]), "r"((A)[2]), "r"((A)[3]), "r"(B0), "r"(B1))

// ---- kernel 0: per-batch top-K via bitonic sort on (-attn, idx) ----
__global__ __launch_bounds__(1024) void topk_kernel(
    const float* __restrict__ attn, const int* __restrict__ num_rt,
    const float* __restrict__ cents, const float* __restrict__ sns)
{
    __shared__ float skey[NNN];
    __shared__ int   sidx[NNN];
    const int b = blockIdx.x, tid = threadIdx.x;
    const int nr = num_rt[b];
    skey[tid] = (tid < nr) ? attn[b * NNN + tid] : -1000000000.0f;
    sidx[tid] = tid;
    __syncthreads();
    for (int size = 2; size <= NNN; size <<= 1)
        for (int stride = size >> 1; stride > 0; stride >>= 1) {
            int j = tid ^ stride;
            if (j > tid) {
                float k1 = skey[tid], k2 = skey[j];
                int   i1 = sidx[tid], i2 = sidx[j];
                bool g  = (k1 < k2) || (k1 == k2 && i1 > i2);
                bool dd = ((tid & size) == 0);
                if (g == dd) { skey[tid] = k2; skey[j] = k1; sidx[tid] = i2; sidx[j] = i1; }
            }
            __syncthreads();
        }
    if (tid < KKK) {
        int i = sidx[tid];
        g_idx[b * KKK + tid] = i;
        float sc = sns[b * 4 + 3];
        float cx = cents[(b * NNN + i) * 3 + 0];
        float cy = cents[(b * NNN + i) * 3 + 1];
        float cz = cents[(b * NNN + i) * 3 + 2];
        if (i < nr) {
            cx = cx * sc + sns[b * 4 + 0];
            cy = cy * sc + sns[b * 4 + 1];
            cz = cz * sc + sns[b * 4 + 2];
        }
        g_cx[b * KKK + tid] = cx;
        g_cy[b * KKK + tid] = cy;
        g_cz[b * KKK + tid] = cz;
    }
    if (tid == 0) g_neff[b] = (nr < KKK) ? nr : KKK;
}

// ---- kernel 1: F = gather(rt) @ W_in + b_in (fp32 SIMT), writes F + hi/lo ----
__global__ __launch_bounds__(256) void gemmF_kernel(
    const float* __restrict__ rt, const float* __restrict__ Win,
    const float* __restrict__ bin)
{
    __shared__ float As[16][128];
    __shared__ float Bs[16][128];
    const int tid = threadIdx.x;
    const int r0 = blockIdx.y * 128;
    const int c0 = blockIdx.x * 128;
    const int tx = tid & 15, ty = tid >> 4;
    const int lrow = tid >> 1, lc = (tid & 1) * 4;
    const int grow = r0 + lrow;
    const float* arow = rt + ((size_t)(grow >> 9) * NNN + g_idx[grow]) * CCC;

    float acc[8][8];
#pragma unroll
    for (int i = 0; i < 8; i++)
#pragma unroll
        for (int j = 0; j < 8; j++) acc[i][j] = 0.f;

    for (int cN = 0; cN < CCC; cN += 16) {
        float4 a0 = *(const float4*)(arow + cN + lc);
        float4 a1 = *(const float4*)(arow + cN + lc + 8);
        int q0 = tid, q1 = tid + 256;
        float4 b0 = *(const float4*)(Win + (size_t)(cN + (q0 >> 5)) * CCC + c0 + (q0 & 31) * 4);
        float4 b1 = *(const float4*)(Win + (size_t)(cN + (q1 >> 5)) * CCC + c0 + (q1 & 31) * 4);
        __syncthreads();
        As[lc + 0][lrow] = a0.x; As[lc + 1][lrow] = a0.y;
        As[lc + 2][lrow] = a0.z; As[lc + 3][lrow] = a0.w;
        As[lc + 8][lrow] = a1.x; As[lc + 9][lrow] = a1.y;
        As[lc +10][lrow] = a1.z; As[lc +11][lrow] = a1.w;
        *(float4*)&Bs[q0 >> 5][(q0 & 31) * 4] = b0;
        *(float4*)&Bs[q1 >> 5][(q1 & 31) * 4] = b1;
        __syncthreads();
#pragma unroll
        for (int kk = 0; kk < 16; kk++) {
            float ra[8], rb[8];
            *(float4*)&ra[0] = *(const float4*)&As[kk][ty * 8];
            *(float4*)&ra[4] = *(const float4*)&As[kk][ty * 8 + 4];
            *(float4*)&rb[0] = *(const float4*)&Bs[kk][tx * 8];
            *(float4*)&rb[4] = *(const float4*)&Bs[kk][tx * 8 + 4];
#pragma unroll
            for (int i = 0; i < 8; i++)
#pragma unroll
                for (int j = 0; j < 8; j++) acc[i][j] += ra[i] * rb[j];
        }
    }
#pragma unroll
    for (int i = 0; i < 8; i++) {
        size_t off = (size_t)(r0 + ty * 8 + i) * CCC + c0 + tx * 8;
        float* dst = g_F + off;
        __nv_bfloat16 hi8[8], lo8[8];
#pragma unroll
        for (int j = 0; j < 8; j++) {
            float v = acc[i][j] + bin[c0 + tx * 8 + j];
            dst[j] = v;
            __nv_bfloat16 h = __float2bfloat16(v);
            hi8[j] = h;
            lo8[j] = __float2bfloat16(v - __bfloat162float(h));
        }
        *(uint4*)(g_Fh + off) = *(const uint4*)hi8;
        *(uint4*)(g_Fl + off) = *(const uint4*)lo8;
    }
}

// ---- kernel 1b: row norms of F ----
__global__ __launch_bounds__(256) void norm_kernel()
{
    const int row  = blockIdx.x * 8 + (threadIdx.x >> 5);
    const int lane = threadIdx.x & 31;
    const float* f = g_F + (size_t)row * CCC;
    float s = 0.f;
    for (int c = lane; c < CCC; c += 32) { float v = f[c]; s += v * v; }
#pragma unroll
    for (int m = 16; m >= 1; m >>= 1) s += __shfl_xor_sync(0xffffffffu, s, m);
    if (lane == 0) g_norm2[row] = s;
}

// ---- kernel 2: mma.sync 2-pass bf16-split GEMM 128x128 tile -> g_D dots ----
// cp.async double-buffered pipeline: loads stream behind mma work.
#define LDA 40
__global__ __launch_bounds__(256) void gemmG_mma_kernel(
    const int* __restrict__ anc, const int* __restrict__ pos,
    const int* __restrict__ neg)
{
    __shared__ __nv_bfloat16 sA[2][128 * LDA];
    __shared__ __nv_bfloat16 sB[2][128 * LDA];
    const int tid = threadIdx.x, lane = tid & 31, wid = tid >> 5;
    const int p = blockIdx.x, mtile = blockIdx.y, ntile = blockIdx.z;
    const int t = p >> 1;
    const int a = anc[t];
    const int c = (p & 1) ? neg[t] : pos[t];
    const int arow0 = a * KKK + mtile * 128;
    const int brow0 = c * KKK + ntile * 128;

    const int m_base = (wid >> 1) * 32;
    const int n_base = (wid & 1) * 64;

    float acc[2][8][4];
#pragma unroll
    for (int mi = 0; mi < 2; mi++)
#pragma unroll
        for (int n8 = 0; n8 < 8; n8++)
#pragma unroll
            for (int r = 0; r < 4; r++) acc[mi][n8][r] = 0.f;

    const int ld_row = tid >> 2, ld_q = (tid & 3) * 8;
    const int ld_row2 = ld_row + 64;

    // issue tile kc into buffer buf (non-blocking)
    auto issue = [&](int kc, int buf) {
        const __nv_bfloat16* Asrc = (kc >= 8) ? g_Fl : g_Fh;
        const int c0 = (kc & 7) * 32;
        uint32_t dA = smem_u32(&sA[buf][0]);
        uint32_t dB = smem_u32(&sB[buf][0]);
        cp_async16(dA + (uint32_t)((ld_row  * LDA + ld_q) * 2), Asrc + (size_t)(arow0 + ld_row ) * CCC + c0 + ld_q);
        cp_async16(dB + (uint32_t)((ld_row  * LDA + ld_q) * 2), g_Fh + (size_t)(brow0 + ld_row ) * CCC + c0 + ld_q);
        cp_async16(dA + (uint32_t)((ld_row2 * LDA + ld_q) * 2), Asrc + (size_t)(arow0 + ld_row2) * CCC + c0 + ld_q);
        cp_async16(dB + (uint32_t)((ld_row2 * LDA + ld_q) * 2), g_Fh + (size_t)(brow0 + ld_row2) * CCC + c0 + ld_q);
        CP_COMMIT();
    };

    issue(0, 0);
    for (int kc = 0; kc < 16; kc++) {
        const int buf = kc & 1;
        if (kc + 1 < 16) {
            issue(kc + 1, buf ^ 1);
            asm volatile("cp.async.wait_group 1;" ::: "memory");
        } else {
            asm volatile("cp.async.wait_group 0;" ::: "memory");
        }
        __syncthreads();
        const uint32_t sa = smem_u32(&sA[buf][0]);
        const uint32_t sb = smem_u32(&sB[buf][0]);
#pragma unroll
        for (int ks = 0; ks < 2; ks++) {
            const int k0 = ks * 16;
            uint32_t af[2][4];
#pragma unroll
            for (int mi = 0; mi < 2; mi++) {
                uint32_t addr = sa + (uint32_t)(((m_base + mi * 16 + (lane & 15)) * LDA + k0 + (lane >> 4) * 8) << 1);
                LDSM_X4(af[mi][0], af[mi][1], af[mi][2], af[mi][3], addr);
            }
            uint32_t bfr[4][4];
#pragma unroll
            for (int nj = 0; nj < 4; nj++) {
                uint32_t addr = sb + (uint32_t)(((n_base + nj * 16 + (lane & 7) + ((lane >> 4) << 3)) * LDA + k0 + ((lane >> 3) & 1) * 8) << 1);
                LDSM_X4(bfr[nj][0], bfr[nj][1], bfr[nj][2], bfr[nj][3], addr);
            }
#pragma unroll
            for (int mi = 0; mi < 2; mi++)
#pragma unroll
                for (int n8 = 0; n8 < 8; n8++)
                    MMA_BF16(acc[mi][n8], af[mi], bfr[n8 >> 1][(n8 & 1) * 2], bfr[n8 >> 1][(n8 & 1) * 2 + 1]);
        }
        __syncthreads();
    }

    // epilogue: store dots to g_D
#pragma unroll
    for (int mi = 0; mi < 2; mi++)
#pragma unroll
        for (int half = 0; half < 2; half++) {
            int grow = mtile * 128 + m_base + mi * 16 + half * 8 + (lane >> 2);
            float* dst = g_D + ((size_t)p * KKK + grow) * KKK + ntile * 128 + n_base + (lane & 3) * 2;
#pragma unroll
            for (int n8 = 0; n8 < 8; n8++) {
                float2 v = make_float2(acc[mi][n8][half * 2 + 0], acc[mi][n8][half * 2 + 1]);
                *(float2*)(dst + n8 * 8) = v;
            }
        }
}

// ---- kernel 2b: exact argmin refinement -> corr, s ----
#define DELTA 2.0f
__global__ __launch_bounds__(256) void refine_kernel(
    const int* __restrict__ anc, const int* __restrict__ pos,
    const int* __restrict__ neg)
{
    __shared__ float snorm[KKK];
    const int p = blockIdx.x, tid = threadIdx.x;
    const int t = p >> 1;
    const int a = anc[t];
    const int c = (p & 1) ? neg[t] : pos[t];
    const int wid = tid >> 5, lane = tid & 31;
    for (int i = tid; i < KKK; i += 256) snorm[i] = g_norm2[c * KKK + i];
    __syncthreads();

    for (int rr = 0; rr < 4; rr++) {
        const int r = blockIdx.y * 32 + rr * 8 + wid;
        const float* drow = g_D + ((size_t)p * KKK + r) * KKK;
        float key[16];
        float bk = 3.4e38f;
#pragma unroll
        for (int i = 0; i < 16; i++) {
            int col = i * 32 + lane;
            key[i] = snorm[col] - 2.f * drow[col];
            bk = fminf(bk, key[i]);
        }
#pragma unroll
        for (int m = 16; m >= 1; m >>= 1) bk = fminf(bk, __shfl_xor_sync(0xffffffffu, bk, m));
        const float thr = bk + DELTA;

        float bestk = 3.4e38f; int bestc = 0; float bestd = 0.f;
        const float* fa = g_F + ((size_t)a * KKK + r) * CCC;
#pragma unroll 1
        for (int i = 0; i < 16; i++) {
            unsigned m = __ballot_sync(0xffffffffu, key[i] <= thr);
            while (m) {
                int b = __ffs(m) - 1; m &= m - 1;
                int col = i * 32 + b;
                const float* fb = g_F + ((size_t)c * KKK + col) * CCC;
                float sd = 0.f;
#pragma unroll
                for (int j = 0; j < 8; j++) sd += fa[lane * 8 + j] * fb[lane * 8 + j];
#pragma unroll
                for (int mm = 16; mm >= 1; mm >>= 1) sd += __shfl_xor_sync(0xffffffffu, sd, mm);
                float ek = snorm[col] - 2.f * sd;
                if (ek < bestk) { bestk = ek; bestc = col; bestd = sd; }
            }
        }
        if (lane == 0) {
            float na = sqrtf(g_norm2[a * KKK + r]);
            float nb = sqrtf(snorm[bestc]);
            g_s[p * KKK + r]    = fmaxf(bestd / (na * nb + 1e-8f), 0.f);
            g_corr[p * KKK + r] = bestc;
        }
    }
}

// ---- kernel 3: geo bitmask + power iteration + sort + MLP ----
__global__ __launch_bounds__(512) void pair_kernel(
    const int* __restrict__ anc, const int* __restrict__ pos,
    const int* __restrict__ neg,
    const float* __restrict__ W1, const float* __restrict__ b1,
    const float* __restrict__ W2, const float* __restrict__ b2,
    float* __restrict__ out, int out_size)
{
    __shared__ unsigned int smask[KKK * 16];
    __shared__ float bufA[KKK * 3];
    __shared__ float bufB[KKK * 3];
    __shared__ float red[33];

    const int p = blockIdx.x, tid = threadIdx.x;
    const int t = p >> 1, n = p & 1;
    const int a = anc[t];
    const int c = n ? neg[t] : pos[t];
    const int neffa = g_neff[a], neffc = g_neff[c];
    const int wid = tid >> 5, lane = tid & 31;

    bufA[tid]           = g_cx[a * KKK + tid];
    bufA[KKK + tid]     = g_cy[a * KKK + tid];
    bufA[2 * KKK + tid] = g_cz[a * KKK + tid];
    {
        int j = g_corr[p * KKK + tid];
        bufB[tid]           = g_cx[c * KKK + j];
        bufB[KKK + tid]     = g_cy[c * KKK + j];
        bufB[2 * KKK + tid] = g_cz[c * KKK + j];
    }
    float sk = g_s[p * KKK + tid];
    __syncthreads();

    for (int kr = 0; kr < 32; kr++) {
        int k = wid * 32 + kr;
        float akx = bufA[k], aky = bufA[KKK + k], akz = bufA[2 * KKK + k];
        float qkx = bufB[k], qky = bufB[KKK + k], qkz = bufB[2 * KKK + k];
        bool rowvalid = (k < neffa);
#pragma unroll 4
        for (int ch = 0; ch < 16; ch++) {
            int l = ch * 32 + lane;
            float dx = akx - bufA[l], dy = aky - bufA[KKK + l], dz = akz - bufA[2 * KKK + l];
            float dp = sqrtf(dx * dx + dy * dy + dz * dz + 1e-12f);
            float ex = qkx - bufB[l], ey = qky - bufB[KKK + l], ez = qkz - bufB[2 * KKK + l];
            float dq = sqrtf(ex * ex + ey * ey + ez * ez + 1e-12f);
            bool geo = (fabsf(dp - dq) < 0.5f) && rowvalid && (l < neffc) && (l != k);
            unsigned bits = __ballot_sync(0xffffffffu, geo);
            if (lane == 0) smask[k * 16 + ch] = bits;
        }
    }
    __syncthreads();

    float* sm_u = bufA;
    float v = (float)(1.0 / sqrt((double)KKK));
    for (int it = 0; it < 20; it++) {
        sm_u[tid] = sk * v;
        __syncthreads();
        float acc = 0.f;
        const unsigned* mrow = &smask[tid * 16];
        const float4* u4 = (const float4*)sm_u;
#pragma unroll 4
        for (int w = 0; w < 16; w++) {
            unsigned bits = mrow[w];
#pragma unroll
            for (int q = 0; q < 8; q++) {
                float4 u = u4[w * 8 + q];
                if (bits & (1u << (q * 4 + 0))) acc += u.x;
                if (bits & (1u << (q * 4 + 1))) acc += u.y;
                if (bits & (1u << (q * 4 + 2))) acc += u.z;
                if (bits & (1u << (q * 4 + 3))) acc += u.w;
            }
        }
        float wv = sk * acc;
        float ss = wv * wv;
#pragma unroll
        for (int m = 16; m >= 1; m >>= 1) ss += __shfl_xor_sync(0xffffffffu, ss, m);
        if (lane == 0) red[wid] = ss;
        __syncthreads();
        if (wid == 0) {
            float x = (lane < 16) ? red[lane] : 0.f;
#pragma unroll
            for (int m = 8; m >= 1; m >>= 1) x += __shfl_xor_sync(0xffffffffu, x, m);
            if (lane == 0) red[32] = sqrtf(x);
        }
        __syncthreads();
        v = wv / (red[32] + 1e-8f);
    }

    float* sv = bufB;
    __syncthreads();
    sv[tid] = v;
    __syncthreads();
    for (int size = 2; size <= KKK; size <<= 1)
        for (int stride = size >> 1; stride > 0; stride >>= 1) {
            int jj = tid ^ stride;
            if (jj > tid) {
                float x1 = sv[tid], x2 = sv[jj];
                bool g  = (x1 < x2);
                bool dd = ((tid & size) == 0);
                if (g == dd) { sv[tid] = x2; sv[jj] = x1; }
            }
            __syncthreads();
        }

    float hacc = b1[tid];
    {
        const float4* sv4 = (const float4*)sv;
#pragma unroll 4
        for (int l4 = 0; l4 < 128; l4++) {
            float4 e = sv4[l4];
            hacc += e.x * W1[(size_t)(l4 * 4 + 0) * KKK + tid];
            hacc += e.y * W1[(size_t)(l4 * 4 + 1) * KKK + tid];
            hacc += e.z * W1[(size_t)(l4 * 4 + 2) * KKK + tid];
            hacc += e.w * W1[(size_t)(l4 * 4 + 3) * KKK + tid];
        }
    }
    float h = fmaxf(hacc, 0.f);
    float contrib = h * W2[tid];
#pragma unroll
    for (int m = 16; m >= 1; m >>= 1) contrib += __shfl_xor_sync(0xffffffffu, contrib, m);
    if (lane == 0) red[wid] = contrib;
    __syncthreads();
    if (tid == 0) {
        float x = 0.f;
        for (int w = 0; w < 16; w++) x += red[w];
        float score = 1.f / (1.f + expf(-(x + b2[0])));
        out[p] = score;
        if (NPAIR + p < out_size) out[NPAIR + p] = (n == 0) ? 1.f : 0.f;
    }
}

extern "C" void kernel_launch(void* const* d_in, const int* in_sizes, int n_in,
                              void* d_out, int out_size) {
    const float* rt    = (const float*)d_in[0];
    const float* cents = (const float*)d_in[1];
    const float* attn  = (const float*)d_in[2];
    const float* sns   = (const float*)d_in[3];
    const int*   nrt   = (const int*)d_in[4];
    const int*   anc   = (const int*)d_in[5];
    const int*   pos   = (const int*)d_in[6];
    const int*   neg   = (const int*)d_in[7];
    const float* Win   = (const float*)d_in[8];
    const float* bin   = (const float*)d_in[9];
    const float* W1    = (const float*)d_in[10];
    const float* b1    = (const float*)d_in[11];
    const float* W2    = (const float*)d_in[12];
    const float* b2    = (const float*)d_in[13];
    float* out = (float*)d_out;

    topk_kernel<<<BB, 1024>>>(attn, nrt, cents, sns);
    gemmF_kernel<<<dim3(CCC / 128, BB * KKK / 128), 256>>>(rt, Win, bin);
    norm_kernel<<<BB * KKK / 8, 256>>>();
    gemmG_mma_kernel<<<dim3(NPAIR, 4, 4), 256>>>(anc, pos, neg);
    refine_kernel<<<dim3(NPAIR, 16), 256>>>(anc, pos, neg);
    pair_kernel<<<NPAIR, 512>>>(anc, pos, neg, W1, b1, W2, b2, out, out_size);
}

// round 8
// speedup vs baseline: 1.6589x; 1.0454x over previous
#include <cuda_runtime.h>
#include <cuda_bf16.h>
#include <cuda_fp16.h>
#include <cstdint>
#include <math.h>

#define BB 64
#define NNN 1024
#define CCC 256
#define KKK 512
#define NPAIR 128

__device__ float g_F[(size_t)BB * KKK * CCC];
__device__ __nv_bfloat16 g_Fh[(size_t)BB * KKK * CCC];
__device__ __nv_bfloat16 g_Fl[(size_t)BB * KKK * CCC];
__device__ __half g_D[(size_t)NPAIR * KKK * KKK];   // fp16 keys
__device__ float g_norm2[BB * KKK];
__device__ float g_cx[BB * KKK];
__device__ float g_cy[BB * KKK];
__device__ float g_cz[BB * KKK];
__device__ int   g_idx[BB * KKK];
__device__ int   g_neff[BB];
__device__ int   g_corr[NPAIR * KKK];
__device__ float g_s[NPAIR * KKK];

__device__ __forceinline__ uint32_t smem_u32(const void* p) {
    uint32_t a;
    asm("{ .reg .u64 t; cvta.to.shared.u64 t, %1; cvt.u32.u64 %0, t; }" : "=r"(a) : "l"(p));
    return a;
}
__device__ __forceinline__ void cp_async16(uint32_t saddr, const void* g) {
    asm volatile("cp.async.cg.shared.global [%0], [%1], 16;" :: "r"(saddr), "l"(g));
}
#define CP_COMMIT() asm volatile("cp.async.commit_group;" ::: "memory")

#define LDSM_X4(R0, R1, R2, R3, ADDR) \
    asm volatile("ldmatrix.sync.aligned.m8n8.x4.shared.b16 {%0,%1,%2,%3}, [%4];" \
        : "=r"(R0), "=r"(R1), "=r"(R2), "=r"(R3) : "r"(ADDR))

#define MMA_BF16(D, A, B0, B1) \
    asm volatile("mma.sync.aligned.m16n8k16.row.col.f32.bf16.bf16.f32 " \
        "{%0,%1,%2,%3}, {%4,%5,%6,%7}, {%8,%9}, {%0,%1,%2,%3};" \
        : "+f"((D)[0]), "+f"((D)[1]), "+f"((D)[2]), "+f"((D)[3]) \
        : "r"((A)[0]), "r"((A)[1]), "r"((A)[2]), "r"((A)[3]), "r"(B0), "r"(B1))

// ---- kernel 0: per-batch top-K via bitonic sort on (-attn, idx); zeroes g_norm2 ----
__global__ __launch_bounds__(1024) void topk_kernel(
    const float* __restrict__ attn, const int* __restrict__ num_rt,
    const float* __restrict__ cents, const float* __restrict__ sns)
{
    __shared__ float skey[NNN];
    __shared__ int   sidx[NNN];
    const int b = blockIdx.x, tid = threadIdx.x;
    const int nr = num_rt[b];
    if (tid < KKK) g_norm2[b * KKK + tid] = 0.f;
    skey[tid] = (tid < nr) ? attn[b * NNN + tid] : -1000000000.0f;
    sidx[tid] = tid;
    __syncthreads();
    for (int size = 2; size <= NNN; size <<= 1)
        for (int stride = size >> 1; stride > 0; stride >>= 1) {
            int j = tid ^ stride;
            if (j > tid) {
                float k1 = skey[tid], k2 = skey[j];
                int   i1 = sidx[tid], i2 = sidx[j];
                bool g  = (k1 < k2) || (k1 == k2 && i1 > i2);
                bool dd = ((tid & size) == 0);
                if (g == dd) { skey[tid] = k2; skey[j] = k1; sidx[tid] = i2; sidx[j] = i1; }
            }
            __syncthreads();
        }
    if (tid < KKK) {
        int i = sidx[tid];
        g_idx[b * KKK + tid] = i;
        float sc = sns[b * 4 + 3];
        float cx = cents[(b * NNN + i) * 3 + 0];
        float cy = cents[(b * NNN + i) * 3 + 1];
        float cz = cents[(b * NNN + i) * 3 + 2];
        if (i < nr) {
            cx = cx * sc + sns[b * 4 + 0];
            cy = cy * sc + sns[b * 4 + 1];
            cz = cz * sc + sns[b * 4 + 2];
        }
        g_cx[b * KKK + tid] = cx;
        g_cy[b * KKK + tid] = cy;
        g_cz[b * KKK + tid] = cz;
    }
    if (tid == 0) g_neff[b] = (nr < KKK) ? nr : KKK;
}

// ---- kernel 1: F = gather(rt) @ W_in + b_in (fp32 SIMT); writes F, hi/lo, norms ----
__global__ __launch_bounds__(256) void gemmF_kernel(
    const float* __restrict__ rt, const float* __restrict__ Win,
    const float* __restrict__ bin)
{
    __shared__ float As[16][128];
    __shared__ float Bs[16][128];
    const int tid = threadIdx.x;
    const int r0 = blockIdx.y * 128;
    const int c0 = blockIdx.x * 128;
    const int tx = tid & 15, ty = tid >> 4;
    const int lrow = tid >> 1, lc = (tid & 1) * 4;
    const int grow = r0 + lrow;
    const float* arow = rt + ((size_t)(grow >> 9) * NNN + g_idx[grow]) * CCC;

    float acc[8][8];
#pragma unroll
    for (int i = 0; i < 8; i++)
#pragma unroll
        for (int j = 0; j < 8; j++) acc[i][j] = 0.f;

    for (int cN = 0; cN < CCC; cN += 16) {
        float4 a0 = *(const float4*)(arow + cN + lc);
        float4 a1 = *(const float4*)(arow + cN + lc + 8);
        int q0 = tid, q1 = tid + 256;
        float4 b0 = *(const float4*)(Win + (size_t)(cN + (q0 >> 5)) * CCC + c0 + (q0 & 31) * 4);
        float4 b1 = *(const float4*)(Win + (size_t)(cN + (q1 >> 5)) * CCC + c0 + (q1 & 31) * 4);
        __syncthreads();
        As[lc + 0][lrow] = a0.x; As[lc + 1][lrow] = a0.y;
        As[lc + 2][lrow] = a0.z; As[lc + 3][lrow] = a0.w;
        As[lc + 8][lrow] = a1.x; As[lc + 9][lrow] = a1.y;
        As[lc +10][lrow] = a1.z; As[lc +11][lrow] = a1.w;
        *(float4*)&Bs[q0 >> 5][(q0 & 31) * 4] = b0;
        *(float4*)&Bs[q1 >> 5][(q1 & 31) * 4] = b1;
        __syncthreads();
#pragma unroll
        for (int kk = 0; kk < 16; kk++) {
            float ra[8], rb[8];
            *(float4*)&ra[0] = *(const float4*)&As[kk][ty * 8];
            *(float4*)&ra[4] = *(const float4*)&As[kk][ty * 8 + 4];
            *(float4*)&rb[0] = *(const float4*)&Bs[kk][tx * 8];
            *(float4*)&rb[4] = *(const float4*)&Bs[kk][tx * 8 + 4];
#pragma unroll
            for (int i = 0; i < 8; i++)
#pragma unroll
                for (int j = 0; j < 8; j++) acc[i][j] += ra[i] * rb[j];
        }
    }
#pragma unroll
    for (int i = 0; i < 8; i++) {
        size_t off = (size_t)(r0 + ty * 8 + i) * CCC + c0 + tx * 8;
        float* dst = g_F + off;
        __nv_bfloat16 hi8[8], lo8[8];
        float ps = 0.f;
#pragma unroll
        for (int j = 0; j < 8; j++) {
            float v = acc[i][j] + bin[c0 + tx * 8 + j];
            dst[j] = v;
            ps += v * v;
            __nv_bfloat16 h = __float2bfloat16(v);
            hi8[j] = h;
            lo8[j] = __float2bfloat16(v - __bfloat162float(h));
        }
        *(uint4*)(g_Fh + off) = *(const uint4*)hi8;
        *(uint4*)(g_Fl + off) = *(const uint4*)lo8;
#pragma unroll
        for (int m = 1; m <= 8; m <<= 1) ps += __shfl_xor_sync(0xffffffffu, ps, m);
        if (tx == 0) atomicAdd(&g_norm2[r0 + ty * 8 + i], ps);
    }
}

// ---- kernel 2: mma.sync 2-pass bf16-split GEMM, 3-stage cp.async, fp16-key epilogue ----
#define LDA 40
#define STG_B (128 * LDA)          // bf16 elems per stage per matrix
#define GDYN_SMEM (3 * STG_B * 2 * 2 + 512)
__global__ __launch_bounds__(256, 2) void gemmG_mma_kernel(
    const int* __restrict__ anc, const int* __restrict__ pos,
    const int* __restrict__ neg)
{
    extern __shared__ char smem[];
    __nv_bfloat16* sA = (__nv_bfloat16*)smem;                 // 3 stages
    __nv_bfloat16* sB = sA + 3 * STG_B;                       // 3 stages
    float* snorm = (float*)(sB + 3 * STG_B);                  // 128 floats

    const int tid = threadIdx.x, lane = tid & 31, wid = tid >> 5;
    const int p = blockIdx.x, mtile = blockIdx.y, ntile = blockIdx.z;
    const int t = p >> 1;
    const int a = anc[t];
    const int c = (p & 1) ? neg[t] : pos[t];

    if (tid < 128) snorm[tid] = g_norm2[c * KKK + ntile * 128 + tid];

    const int m_base = (wid >> 1) * 32;
    const int n_base = (wid & 1) * 64;

    float acc[2][8][4];
#pragma unroll
    for (int mi = 0; mi < 2; mi++)
#pragma unroll
        for (int n8 = 0; n8 < 8; n8++)
#pragma unroll
            for (int r = 0; r < 4; r++) acc[mi][n8][r] = 0.f;

    const int ld_row = tid >> 2, ld_q = (tid & 3) * 8;
    const __nv_bfloat16* gAhi = g_Fh + (size_t)(a * KKK + mtile * 128) * CCC;
    const __nv_bfloat16* gAlo = g_Fl + (size_t)(a * KKK + mtile * 128) * CCC;
    const __nv_bfloat16* gB   = g_Fh + (size_t)(c * KKK + ntile * 128) * CCC;
    const size_t go1 = (size_t)ld_row * CCC + ld_q;
    const size_t go2 = (size_t)(ld_row + 64) * CCC + ld_q;
    const uint32_t so1 = (uint32_t)((ld_row * LDA + ld_q) * 2);
    const uint32_t so2 = (uint32_t)(((ld_row + 64) * LDA + ld_q) * 2);
    const uint32_t sAu = smem_u32(sA), sBu = smem_u32(sB);

#define ISSUE(KC, ST) do { \
        const __nv_bfloat16* Asrc = ((KC) >= 8 ? gAlo : gAhi) + ((KC) & 7) * 32; \
        const __nv_bfloat16* Bsrc = gB + ((KC) & 7) * 32; \
        uint32_t dA = sAu + (uint32_t)(ST) * (STG_B * 2); \
        uint32_t dB = sBu + (uint32_t)(ST) * (STG_B * 2); \
        cp_async16(dA + so1, Asrc + go1); \
        cp_async16(dB + so1, Bsrc + go1); \
        cp_async16(dA + so2, Asrc + go2); \
        cp_async16(dB + so2, Bsrc + go2); \
        CP_COMMIT(); \
    } while (0)

    ISSUE(0, 0);
    ISSUE(1, 1);
    for (int kc = 0; kc < 16; kc++) {
        const int buf = kc % 3;
        if (kc + 2 < 16) {
            ISSUE(kc + 2, (kc + 2) % 3);
            asm volatile("cp.async.wait_group 2;" ::: "memory");
        } else if (kc + 1 < 16) {
            asm volatile("cp.async.wait_group 1;" ::: "memory");
        } else {
            asm volatile("cp.async.wait_group 0;" ::: "memory");
        }
        __syncthreads();
        const uint32_t sa = sAu + (uint32_t)buf * (STG_B * 2);
        const uint32_t sb = sBu + (uint32_t)buf * (STG_B * 2);
#pragma unroll
        for (int ks = 0; ks < 2; ks++) {
            const int k0 = ks * 16;
            uint32_t af[2][4];
#pragma unroll
            for (int mi = 0; mi < 2; mi++) {
                uint32_t addr = sa + (uint32_t)(((m_base + mi * 16 + (lane & 15)) * LDA + k0 + (lane >> 4) * 8) << 1);
                LDSM_X4(af[mi][0], af[mi][1], af[mi][2], af[mi][3], addr);
            }
            uint32_t bfr[4][4];
#pragma unroll
            for (int nj = 0; nj < 4; nj++) {
                uint32_t addr = sb + (uint32_t)(((n_base + nj * 16 + (lane & 7) + ((lane >> 4) << 3)) * LDA + k0 + ((lane >> 3) & 1) * 8) << 1);
                LDSM_X4(bfr[nj][0], bfr[nj][1], bfr[nj][2], bfr[nj][3], addr);
            }
#pragma unroll
            for (int mi = 0; mi < 2; mi++)
#pragma unroll
                for (int n8 = 0; n8 < 8; n8++)
                    MMA_BF16(acc[mi][n8], af[mi], bfr[n8 >> 1][(n8 & 1) * 2], bfr[n8 >> 1][(n8 & 1) * 2 + 1]);
        }
        __syncthreads();
    }
#undef ISSUE

    // epilogue: compute fp16 keys = ||b||^2 - 2*dot and store
#pragma unroll
    for (int mi = 0; mi < 2; mi++)
#pragma unroll
        for (int half = 0; half < 2; half++) {
            int grow = mtile * 128 + m_base + mi * 16 + half * 8 + (lane >> 2);
            int lc0 = n_base + (lane & 3) * 2;
            __half* dst = g_D + ((size_t)p * KKK + grow) * KKK + ntile * 128 + lc0;
#pragma unroll
            for (int n8 = 0; n8 < 8; n8++) {
                float k0v = snorm[lc0 + n8 * 8]     - 2.f * acc[mi][n8][half * 2 + 0];
                float k1v = snorm[lc0 + n8 * 8 + 1] - 2.f * acc[mi][n8][half * 2 + 1];
                *(__half2*)(dst + n8 * 8) = __floats2half2_rn(k0v, k1v);
            }
        }
}

// ---- kernel 2b: exact argmin refinement from fp16 keys -> corr, s ----
#define DELTA 3.0f
__global__ __launch_bounds__(256) void refine_kernel(
    const int* __restrict__ anc, const int* __restrict__ pos,
    const int* __restrict__ neg)
{
    __shared__ float snorm[KKK];
    const int p = blockIdx.x, tid = threadIdx.x;
    const int t = p >> 1;
    const int a = anc[t];
    const int c = (p & 1) ? neg[t] : pos[t];
    const int wid = tid >> 5, lane = tid & 31;
    for (int i = tid; i < KKK; i += 256) snorm[i] = g_norm2[c * KKK + i];
    __syncthreads();

    for (int rr = 0; rr < 4; rr++) {
        const int r = blockIdx.y * 32 + rr * 8 + wid;
        const __half* drow = g_D + ((size_t)p * KKK + r) * KKK;
        float key[16];
        float bk = 3.4e38f;
#pragma unroll
        for (int i = 0; i < 16; i++) {
            key[i] = __half2float(drow[i * 32 + lane]);
            bk = fminf(bk, key[i]);
        }
#pragma unroll
        for (int m = 16; m >= 1; m >>= 1) bk = fminf(bk, __shfl_xor_sync(0xffffffffu, bk, m));
        const float thr = bk + DELTA;

        float bestk = 3.4e38f; int bestc = 0; float bestd = 0.f;
        const float* fa = g_F + ((size_t)a * KKK + r) * CCC;
#pragma unroll 1
        for (int i = 0; i < 16; i++) {
            unsigned m = __ballot_sync(0xffffffffu, key[i] <= thr);
            while (m) {
                int b = __ffs(m) - 1; m &= m - 1;
                int col = i * 32 + b;
                const float* fb = g_F + ((size_t)c * KKK + col) * CCC;
                float sd = 0.f;
#pragma unroll
                for (int j = 0; j < 8; j++) sd += fa[lane * 8 + j] * fb[lane * 8 + j];
#pragma unroll
                for (int mm = 16; mm >= 1; mm >>= 1) sd += __shfl_xor_sync(0xffffffffu, sd, mm);
                float ek = snorm[col] - 2.f * sd;
                if (ek < bestk) { bestk = ek; bestc = col; bestd = sd; }
            }
        }
        if (lane == 0) {
            float na = sqrtf(g_norm2[a * KKK + r]);
            float nb = sqrtf(snorm[bestc]);
            g_s[p * KKK + r]    = fmaxf(bestd / (na * nb + 1e-8f), 0.f);
            g_corr[p * KKK + r] = bestc;
        }
    }
}

// ---- kernel 3: geo bitmask + power iteration + sort + MLP ----
__global__ __launch_bounds__(512) void pair_kernel(
    const int* __restrict__ anc, const int* __restrict__ pos,
    const int* __restrict__ neg,
    const float* __restrict__ W1, const float* __restrict__ b1,
    const float* __restrict__ W2, const float* __restrict__ b2,
    float* __restrict__ out, int out_size)
{
    __shared__ unsigned int smask[KKK * 16];
    __shared__ float bufA[KKK * 3];
    __shared__ float bufB[KKK * 3];
    __shared__ float red[33];

    const int p = blockIdx.x, tid = threadIdx.x;
    const int t = p >> 1, n = p & 1;
    const int a = anc[t];
    const int c = n ? neg[t] : pos[t];
    const int neffa = g_neff[a], neffc = g_neff[c];
    const int wid = tid >> 5, lane = tid & 31;

    bufA[tid]           = g_cx[a * KKK + tid];
    bufA[KKK + tid]     = g_cy[a * KKK + tid];
    bufA[2 * KKK + tid] = g_cz[a * KKK + tid];
    {
        int j = g_corr[p * KKK + tid];
        bufB[tid]           = g_cx[c * KKK + j];
        bufB[KKK + tid]     = g_cy[c * KKK + j];
        bufB[2 * KKK + tid] = g_cz[c * KKK + j];
    }
    float sk = g_s[p * KKK + tid];
    __syncthreads();

    for (int kr = 0; kr < 32; kr++) {
        int k = wid * 32 + kr;
        float akx = bufA[k], aky = bufA[KKK + k], akz = bufA[2 * KKK + k];
        float qkx = bufB[k], qky = bufB[KKK + k], qkz = bufB[2 * KKK + k];
        bool rowvalid = (k < neffa);
#pragma unroll 4
        for (int ch = 0; ch < 16; ch++) {
            int l = ch * 32 + lane;
            float dx = akx - bufA[l], dy = aky - bufA[KKK + l], dz = akz - bufA[2 * KKK + l];
            float dp = sqrtf(dx * dx + dy * dy + dz * dz + 1e-12f);
            float ex = qkx - bufB[l], ey = qky - bufB[KKK + l], ez = qkz - bufB[2 * KKK + l];
            float dq = sqrtf(ex * ex + ey * ey + ez * ez + 1e-12f);
            bool geo = (fabsf(dp - dq) < 0.5f) && rowvalid && (l < neffc) && (l != k);
            unsigned bits = __ballot_sync(0xffffffffu, geo);
            if (lane == 0) smask[k * 16 + ch] = bits;
        }
    }
    __syncthreads();

    float* sm_u = bufA;
    float v = (float)(1.0 / sqrt((double)KKK));
    for (int it = 0; it < 20; it++) {
        sm_u[tid] = sk * v;
        __syncthreads();
        float acc = 0.f;
        const unsigned* mrow = &smask[tid * 16];
        const float4* u4 = (const float4*)sm_u;
#pragma unroll 4
        for (int w = 0; w < 16; w++) {
            unsigned bits = mrow[w];
#pragma unroll
            for (int q = 0; q < 8; q++) {
                float4 u = u4[w * 8 + q];
                if (bits & (1u << (q * 4 + 0))) acc += u.x;
                if (bits & (1u << (q * 4 + 1))) acc += u.y;
                if (bits & (1u << (q * 4 + 2))) acc += u.z;
                if (bits & (1u << (q * 4 + 3))) acc += u.w;
            }
        }
        float wv = sk * acc;
        float ss = wv * wv;
#pragma unroll
        for (int m = 16; m >= 1; m >>= 1) ss += __shfl_xor_sync(0xffffffffu, ss, m);
        if (lane == 0) red[wid] = ss;
        __syncthreads();
        if (wid == 0) {
            float x = (lane < 16) ? red[lane] : 0.f;
#pragma unroll
            for (int m = 8; m >= 1; m >>= 1) x += __shfl_xor_sync(0xffffffffu, x, m);
            if (lane == 0) red[32] = sqrtf(x);
        }
        __syncthreads();
        v = wv / (red[32] + 1e-8f);
    }

    float* sv = bufB;
    __syncthreads();
    sv[tid] = v;
    __syncthreads();
    for (int size = 2; size <= KKK; size <<= 1)
        for (int stride = size >> 1; stride > 0; stride >>= 1) {
            int jj = tid ^ stride;
            if (jj > tid) {
                float x1 = sv[tid], x2 = sv[jj];
                bool g  = (x1 < x2);
                bool dd = ((tid & size) == 0);
                if (g == dd) { sv[tid] = x2; sv[jj] = x1; }
            }
            __syncthreads();
        }

    float hacc = b1[tid];
    {
        const float4* sv4 = (const float4*)sv;
#pragma unroll 4
        for (int l4 = 0; l4 < 128; l4++) {
            float4 e = sv4[l4];
            hacc += e.x * W1[(size_t)(l4 * 4 + 0) * KKK + tid];
            hacc += e.y * W1[(size_t)(l4 * 4 + 1) * KKK + tid];
            hacc += e.z * W1[(size_t)(l4 * 4 + 2) * KKK + tid];
            hacc += e.w * W1[(size_t)(l4 * 4 + 3) * KKK + tid];
        }
    }
    float h = fmaxf(hacc, 0.f);
    float contrib = h * W2[tid];
#pragma unroll
    for (int m = 16; m >= 1; m >>= 1) contrib += __shfl_xor_sync(0xffffffffu, contrib, m);
    if (lane == 0) red[wid] = contrib;
    __syncthreads();
    if (tid == 0) {
        float x = 0.f;
        for (int w = 0; w < 16; w++) x += red[w];
        float score = 1.f / (1.f + expf(-(x + b2[0])));
        out[p] = score;
        if (NPAIR + p < out_size) out[NPAIR + p] = (n == 0) ? 1.f : 0.f;
    }
}

extern "C" void kernel_launch(void* const* d_in, const int* in_sizes, int n_in,
                              void* d_out, int out_size) {
    const float* rt    = (const float*)d_in[0];
    const float* cents = (const float*)d_in[1];
    const float* attn  = (const float*)d_in[2];
    const float* sns   = (const float*)d_in[3];
    const int*   nrt   = (const int*)d_in[4];
    const int*   anc   = (const int*)d_in[5];
    const int*   pos   = (const int*)d_in[6];
    const int*   neg   = (const int*)d_in[7];
    const float* Win   = (const float*)d_in[8];
    const float* bin   = (const float*)d_in[9];
    const float* W1    = (const float*)d_in[10];
    const float* b1    = (const float*)d_in[11];
    const float* W2    = (const float*)d_in[12];
    const float* b2    = (const float*)d_in[13];
    float* out = (float*)d_out;

    cudaFuncSetAttribute(gemmG_mma_kernel, cudaFuncAttributeMaxDynamicSharedMemorySize, GDYN_SMEM);

    topk_kernel<<<BB, 1024>>>(attn, nrt, cents, sns);
    gemmF_kernel<<<dim3(CCC / 128, BB * KKK / 128), 256>>>(rt, Win, bin);
    gemmG_mma_kernel<<<dim3(NPAIR, 4, 4), 256, GDYN_SMEM>>>(anc, pos, neg);
    refine_kernel<<<dim3(NPAIR, 16), 256>>>(anc, pos, neg);
    pair_kernel<<<NPAIR, 512>>>(anc, pos, neg, W1, b1, W2, b2, out, out_size);
}

// round 9
// speedup vs baseline: 1.6854x; 1.0160x over previous
#include <cuda_runtime.h>
#include <cuda_bf16.h>
#include <cuda_fp16.h>
#include <cstdint>
#include <math.h>

#define BB 64
#define NNN 1024
#define CCC 256
#define KKK 512
#define NPAIR 128

__device__ float g_F[(size_t)BB * KKK * CCC];
__device__ __nv_bfloat16 g_Fh[(size_t)BB * KKK * CCC];
__device__ __nv_bfloat16 g_Fl[(size_t)BB * KKK * CCC];
__device__ __half g_D[(size_t)NPAIR * KKK * KKK];   // fp16 keys
__device__ float g_norm2[BB * KKK];
__device__ float g_cx[BB * KKK];
__device__ float g_cy[BB * KKK];
__device__ float g_cz[BB * KKK];
__device__ int   g_idx[BB * KKK];
__device__ int   g_neff[BB];
__device__ int   g_corr[NPAIR * KKK];
__device__ float g_s[NPAIR * KKK];

__device__ __forceinline__ uint32_t smem_u32(const void* p) {
    uint32_t a;
    asm("{ .reg .u64 t; cvta.to.shared.u64 t, %1; cvt.u32.u64 %0, t; }" : "=r"(a) : "l"(p));
    return a;
}
__device__ __forceinline__ void cp_async16(uint32_t saddr, const void* g) {
    asm volatile("cp.async.cg.shared.global [%0], [%1], 16;" :: "r"(saddr), "l"(g));
}
#define CP_COMMIT() asm volatile("cp.async.commit_group;" ::: "memory")

#define LDSM_X4(R0, R1, R2, R3, ADDR) \
    asm volatile("ldmatrix.sync.aligned.m8n8.x4.shared.b16 {%0,%1,%2,%3}, [%4];" \
        : "=r"(R0), "=r"(R1), "=r"(R2), "=r"(R3) : "r"(ADDR))

#define MMA_BF16(D, A, B0, B1) \
    asm volatile("mma.sync.aligned.m16n8k16.row.col.f32.bf16.bf16.f32 " \
        "{%0,%1,%2,%3}, {%4,%5,%6,%7}, {%8,%9}, {%0,%1,%2,%3};" \
        : "+f"((D)[0]), "+f"((D)[1]), "+f"((D)[2]), "+f"((D)[3]) \
        : "r"((A)[0]), "r"((A)[1]), "r"((A)[2]), "r"((A)[3]), "r"(B0), "r"(B1))

// ---- kernel 0: per-batch top-K via bitonic sort on (-attn, idx); zeroes g_norm2 ----
__global__ __launch_bounds__(1024) void topk_kernel(
    const float* __restrict__ attn, const int* __restrict__ num_rt,
    const float* __restrict__ cents, const float* __restrict__ sns)
{
    __shared__ float skey[NNN];
    __shared__ int   sidx[NNN];
    const int b = blockIdx.x, tid = threadIdx.x;
    const int nr = num_rt[b];
    if (tid < KKK) g_norm2[b * KKK + tid] = 0.f;
    skey[tid] = (tid < nr) ? attn[b * NNN + tid] : -1000000000.0f;
    sidx[tid] = tid;
    __syncthreads();
    for (int size = 2; size <= NNN; size <<= 1)
        for (int stride = size >> 1; stride > 0; stride >>= 1) {
            int j = tid ^ stride;
            if (j > tid) {
                float k1 = skey[tid], k2 = skey[j];
                int   i1 = sidx[tid], i2 = sidx[j];
                bool g  = (k1 < k2) || (k1 == k2 && i1 > i2);
                bool dd = ((tid & size) == 0);
                if (g == dd) { skey[tid] = k2; skey[j] = k1; sidx[tid] = i2; sidx[j] = i1; }
            }
            __syncthreads();
        }
    if (tid < KKK) {
        int i = sidx[tid];
        g_idx[b * KKK + tid] = i;
        float sc = sns[b * 4 + 3];
        float cx = cents[(b * NNN + i) * 3 + 0];
        float cy = cents[(b * NNN + i) * 3 + 1];
        float cz = cents[(b * NNN + i) * 3 + 2];
        if (i < nr) {
            cx = cx * sc + sns[b * 4 + 0];
            cy = cy * sc + sns[b * 4 + 1];
            cz = cz * sc + sns[b * 4 + 2];
        }
        g_cx[b * KKK + tid] = cx;
        g_cy[b * KKK + tid] = cy;
        g_cz[b * KKK + tid] = cz;
    }
    if (tid == 0) g_neff[b] = (nr < KKK) ? nr : KKK;
}

// ---- kernel 1: F = gather(rt) @ W_in + b_in (fp32 SIMT, reg-prefetch pipeline) ----
__global__ __launch_bounds__(256) void gemmF_kernel(
    const float* __restrict__ rt, const float* __restrict__ Win,
    const float* __restrict__ bin)
{
    __shared__ float As[16][128];
    __shared__ float Bs[16][128];
    const int tid = threadIdx.x;
    const int r0 = blockIdx.y * 128;
    const int c0 = blockIdx.x * 128;
    const int tx = tid & 15, ty = tid >> 4;
    const int lrow = tid >> 1, lc = (tid & 1) * 4;
    const int grow = r0 + lrow;
    const float* arow = rt + ((size_t)(grow >> 9) * NNN + g_idx[grow]) * CCC;
    const int q0 = tid, q1 = tid + 256;
    const float* wp0 = Win + (size_t)(q0 >> 5) * CCC + c0 + (q0 & 31) * 4;
    const float* wp1 = Win + (size_t)(q1 >> 5) * CCC + c0 + (q1 & 31) * 4;

    float acc[8][8];
#pragma unroll
    for (int i = 0; i < 8; i++)
#pragma unroll
        for (int j = 0; j < 8; j++) acc[i][j] = 0.f;

    // prefetch tile 0
    float4 a0 = *(const float4*)(arow + lc);
    float4 a1 = *(const float4*)(arow + lc + 8);
    float4 b0 = *(const float4*)(wp0);
    float4 b1 = *(const float4*)(wp1);

    for (int cN = 0; cN < CCC; cN += 16) {
        __syncthreads();
        As[lc + 0][lrow] = a0.x; As[lc + 1][lrow] = a0.y;
        As[lc + 2][lrow] = a0.z; As[lc + 3][lrow] = a0.w;
        As[lc + 8][lrow] = a1.x; As[lc + 9][lrow] = a1.y;
        As[lc +10][lrow] = a1.z; As[lc +11][lrow] = a1.w;
        *(float4*)&Bs[q0 >> 5][(q0 & 31) * 4] = b0;
        *(float4*)&Bs[q1 >> 5][(q1 & 31) * 4] = b1;
        __syncthreads();
        if (cN + 16 < CCC) {
            a0 = *(const float4*)(arow + cN + 16 + lc);
            a1 = *(const float4*)(arow + cN + 16 + lc + 8);
            b0 = *(const float4*)(wp0 + (size_t)(cN + 16) * CCC);
            b1 = *(const float4*)(wp1 + (size_t)(cN + 16) * CCC);
        }
#pragma unroll
        for (int kk = 0; kk < 16; kk++) {
            float ra[8], rb[8];
            *(float4*)&ra[0] = *(const float4*)&As[kk][ty * 8];
            *(float4*)&ra[4] = *(const float4*)&As[kk][ty * 8 + 4];
            *(float4*)&rb[0] = *(const float4*)&Bs[kk][tx * 8];
            *(float4*)&rb[4] = *(const float4*)&Bs[kk][tx * 8 + 4];
#pragma unroll
            for (int i = 0; i < 8; i++)
#pragma unroll
                for (int j = 0; j < 8; j++) acc[i][j] += ra[i] * rb[j];
        }
    }
#pragma unroll
    for (int i = 0; i < 8; i++) {
        size_t off = (size_t)(r0 + ty * 8 + i) * CCC + c0 + tx * 8;
        float* dst = g_F + off;
        __nv_bfloat16 hi8[8], lo8[8];
        float ps = 0.f;
#pragma unroll
        for (int j = 0; j < 8; j++) {
            float v = acc[i][j] + bin[c0 + tx * 8 + j];
            dst[j] = v;
            ps += v * v;
            __nv_bfloat16 h = __float2bfloat16(v);
            hi8[j] = h;
            lo8[j] = __float2bfloat16(v - __bfloat162float(h));
        }
        *(uint4*)(g_Fh + off) = *(const uint4*)hi8;
        *(uint4*)(g_Fl + off) = *(const uint4*)lo8;
#pragma unroll
        for (int m = 1; m <= 8; m <<= 1) ps += __shfl_xor_sync(0xffffffffu, ps, m);
        if (tx == 0) atomicAdd(&g_norm2[r0 + ty * 8 + i], ps);
    }
}

// ---- kernel 2: mma.sync 2-pass bf16-split GEMM, 3-stage cp.async, fp16-key epilogue ----
#define LDA 40
#define STG_B (128 * LDA)
#define GDYN_SMEM (3 * STG_B * 2 * 2 + 512)
__global__ __launch_bounds__(256, 2) void gemmG_mma_kernel(
    const int* __restrict__ anc, const int* __restrict__ pos,
    const int* __restrict__ neg)
{
    extern __shared__ char smem[];
    __nv_bfloat16* sA = (__nv_bfloat16*)smem;
    __nv_bfloat16* sB = sA + 3 * STG_B;
    float* snorm = (float*)(sB + 3 * STG_B);

    const int tid = threadIdx.x, lane = tid & 31, wid = tid >> 5;
    const int p = blockIdx.x, mtile = blockIdx.y, ntile = blockIdx.z;
    const int t = p >> 1;
    const int a = anc[t];
    const int c = (p & 1) ? neg[t] : pos[t];

    if (tid < 128) snorm[tid] = g_norm2[c * KKK + ntile * 128 + tid];

    const int m_base = (wid >> 1) * 32;
    const int n_base = (wid & 1) * 64;

    float acc[2][8][4];
#pragma unroll
    for (int mi = 0; mi < 2; mi++)
#pragma unroll
        for (int n8 = 0; n8 < 8; n8++)
#pragma unroll
            for (int r = 0; r < 4; r++) acc[mi][n8][r] = 0.f;

    const int ld_row = tid >> 2, ld_q = (tid & 3) * 8;
    const __nv_bfloat16* gAhi = g_Fh + (size_t)(a * KKK + mtile * 128) * CCC;
    const __nv_bfloat16* gAlo = g_Fl + (size_t)(a * KKK + mtile * 128) * CCC;
    const __nv_bfloat16* gB   = g_Fh + (size_t)(c * KKK + ntile * 128) * CCC;
    const size_t go1 = (size_t)ld_row * CCC + ld_q;
    const size_t go2 = (size_t)(ld_row + 64) * CCC + ld_q;
    const uint32_t so1 = (uint32_t)((ld_row * LDA + ld_q) * 2);
    const uint32_t so2 = (uint32_t)(((ld_row + 64) * LDA + ld_q) * 2);
    const uint32_t sAu = smem_u32(sA), sBu = smem_u32(sB);

#define ISSUE(KC, ST) do { \
        const __nv_bfloat16* Asrc = ((KC) >= 8 ? gAlo : gAhi) + ((KC) & 7) * 32; \
        const __nv_bfloat16* Bsrc = gB + ((KC) & 7) * 32; \
        uint32_t dA = sAu + (uint32_t)(ST) * (STG_B * 2); \
        uint32_t dB = sBu + (uint32_t)(ST) * (STG_B * 2); \
        cp_async16(dA + so1, Asrc + go1); \
        cp_async16(dB + so1, Bsrc + go1); \
        cp_async16(dA + so2, Asrc + go2); \
        cp_async16(dB + so2, Bsrc + go2); \
        CP_COMMIT(); \
    } while (0)

    ISSUE(0, 0);
    ISSUE(1, 1);
    for (int kc = 0; kc < 16; kc++) {
        const int buf = kc % 3;
        if (kc + 2 < 16) {
            ISSUE(kc + 2, (kc + 2) % 3);
            asm volatile("cp.async.wait_group 2;" ::: "memory");
        } else if (kc + 1 < 16) {
            asm volatile("cp.async.wait_group 1;" ::: "memory");
        } else {
            asm volatile("cp.async.wait_group 0;" ::: "memory");
        }
        __syncthreads();
        const uint32_t sa = sAu + (uint32_t)buf * (STG_B * 2);
        const uint32_t sb = sBu + (uint32_t)buf * (STG_B * 2);
#pragma unroll
        for (int ks = 0; ks < 2; ks++) {
            const int k0 = ks * 16;
            uint32_t af[2][4];
#pragma unroll
            for (int mi = 0; mi < 2; mi++) {
                uint32_t addr = sa + (uint32_t)(((m_base + mi * 16 + (lane & 15)) * LDA + k0 + (lane >> 4) * 8) << 1);
                LDSM_X4(af[mi][0], af[mi][1], af[mi][2], af[mi][3], addr);
            }
            uint32_t bfr[4][4];
#pragma unroll
            for (int nj = 0; nj < 4; nj++) {
                uint32_t addr = sb + (uint32_t)(((n_base + nj * 16 + (lane & 7) + ((lane >> 4) << 3)) * LDA + k0 + ((lane >> 3) & 1) * 8) << 1);
                LDSM_X4(bfr[nj][0], bfr[nj][1], bfr[nj][2], bfr[nj][3], addr);
            }
#pragma unroll
            for (int mi = 0; mi < 2; mi++)
#pragma unroll
                for (int n8 = 0; n8 < 8; n8++)
                    MMA_BF16(acc[mi][n8], af[mi], bfr[n8 >> 1][(n8 & 1) * 2], bfr[n8 >> 1][(n8 & 1) * 2 + 1]);
        }
        __syncthreads();
    }
#undef ISSUE

#pragma unroll
    for (int mi = 0; mi < 2; mi++)
#pragma unroll
        for (int half = 0; half < 2; half++) {
            int grow = mtile * 128 + m_base + mi * 16 + half * 8 + (lane >> 2);
            int lc0 = n_base + (lane & 3) * 2;
            __half* dst = g_D + ((size_t)p * KKK + grow) * KKK + ntile * 128 + lc0;
#pragma unroll
            for (int n8 = 0; n8 < 8; n8++) {
                float k0v = snorm[lc0 + n8 * 8]     - 2.f * acc[mi][n8][half * 2 + 0];
                float k1v = snorm[lc0 + n8 * 8 + 1] - 2.f * acc[mi][n8][half * 2 + 1];
                *(__half2*)(dst + n8 * 8) = __floats2half2_rn(k0v, k1v);
            }
        }
}

// ---- kernel 2b: exact argmin refinement from fp16 keys (vectorized loads) ----
#define DELTA 3.0f
__global__ __launch_bounds__(256) void refine_kernel(
    const int* __restrict__ anc, const int* __restrict__ pos,
    const int* __restrict__ neg)
{
    __shared__ float snorm[KKK];
    const int p = blockIdx.x, tid = threadIdx.x;
    const int t = p >> 1;
    const int a = anc[t];
    const int c = (p & 1) ? neg[t] : pos[t];
    const int wid = tid >> 5, lane = tid & 31;
    for (int i = tid; i < KKK; i += 256) snorm[i] = g_norm2[c * KKK + i];
    __syncthreads();

    for (int rr = 0; rr < 4; rr++) {
        const int r = blockIdx.y * 32 + rr * 8 + wid;
        const uint4* drow = (const uint4*)(g_D + ((size_t)p * KKK + r) * KKK);
        // lane owns 16 contiguous keys: cols [lane*16, lane*16+16)
        uint4 v0 = drow[lane * 2];
        uint4 v1 = drow[lane * 2 + 1];
        float key[16];
        {
            const uint32_t w[8] = {v0.x, v0.y, v0.z, v0.w, v1.x, v1.y, v1.z, v1.w};
#pragma unroll
            for (int q = 0; q < 8; q++) {
                __half2 h2 = *(const __half2*)&w[q];
                float2 f2 = __half22float2(h2);
                key[q * 2 + 0] = f2.x;
                key[q * 2 + 1] = f2.y;
            }
        }
        float bk = 3.4e38f;
#pragma unroll
        for (int j = 0; j < 16; j++) bk = fminf(bk, key[j]);
#pragma unroll
        for (int m = 16; m >= 1; m >>= 1) bk = fminf(bk, __shfl_xor_sync(0xffffffffu, bk, m));
        const float thr = bk + DELTA;

        unsigned mymask = 0;
#pragma unroll
        for (int j = 0; j < 16; j++)
            if (key[j] <= thr) mymask |= (1u << j);

        float bestk = 3.4e38f; int bestc = 0; float bestd = 0.f;
        const float* fa = g_F + ((size_t)a * KKK + r) * CCC;
        unsigned active = __ballot_sync(0xffffffffu, mymask != 0);
        while (active) {
            int src = __ffs(active) - 1; active &= active - 1;
            unsigned mk = __shfl_sync(0xffffffffu, mymask, src);
            while (mk) {
                int j = __ffs(mk) - 1; mk &= mk - 1;
                int col = src * 16 + j;
                const float* fb = g_F + ((size_t)c * KKK + col) * CCC;
                float sd = 0.f;
#pragma unroll
                for (int q = 0; q < 8; q++) sd += fa[lane * 8 + q] * fb[lane * 8 + q];
#pragma unroll
                for (int mm = 16; mm >= 1; mm >>= 1) sd += __shfl_xor_sync(0xffffffffu, sd, mm);
                float ek = snorm[col] - 2.f * sd;
                if (ek < bestk) { bestk = ek; bestc = col; bestd = sd; }
            }
        }
        if (lane == 0) {
            float na = sqrtf(g_norm2[a * KKK + r]);
            float nb = sqrtf(snorm[bestc]);
            g_s[p * KKK + r]    = fmaxf(bestd / (na * nb + 1e-8f), 0.f);
            g_corr[p * KKK + r] = bestc;
        }
    }
}

// ---- kernel 3: geo bitmask + power iteration + sort + MLP ----
__global__ __launch_bounds__(512) void pair_kernel(
    const int* __restrict__ anc, const int* __restrict__ pos,
    const int* __restrict__ neg,
    const float* __restrict__ W1, const float* __restrict__ b1,
    const float* __restrict__ W2, const float* __restrict__ b2,
    float* __restrict__ out, int out_size)
{
    __shared__ unsigned int smask[KKK * 16];
    __shared__ float bufA[KKK * 3];
    __shared__ float bufB[KKK * 3];
    __shared__ float red[33];

    const int p = blockIdx.x, tid = threadIdx.x;
    const int t = p >> 1, n = p & 1;
    const int a = anc[t];
    const int c = n ? neg[t] : pos[t];
    const int neffa = g_neff[a], neffc = g_neff[c];
    const int wid = tid >> 5, lane = tid & 31;

    bufA[tid]           = g_cx[a * KKK + tid];
    bufA[KKK + tid]     = g_cy[a * KKK + tid];
    bufA[2 * KKK + tid] = g_cz[a * KKK + tid];
    {
        int j = g_corr[p * KKK + tid];
        bufB[tid]           = g_cx[c * KKK + j];
        bufB[KKK + tid]     = g_cy[c * KKK + j];
        bufB[2 * KKK + tid] = g_cz[c * KKK + j];
    }
    float sk = g_s[p * KKK + tid];
    __syncthreads();

    for (int kr = 0; kr < 32; kr++) {
        int k = wid * 32 + kr;
        float akx = bufA[k], aky = bufA[KKK + k], akz = bufA[2 * KKK + k];
        float qkx = bufB[k], qky = bufB[KKK + k], qkz = bufB[2 * KKK + k];
        bool rowvalid = (k < neffa);
#pragma unroll 4
        for (int ch = 0; ch < 16; ch++) {
            int l = ch * 32 + lane;
            float dx = akx - bufA[l], dy = aky - bufA[KKK + l], dz = akz - bufA[2 * KKK + l];
            float dp = sqrtf(dx * dx + dy * dy + dz * dz + 1e-12f);
            float ex = qkx - bufB[l], ey = qky - bufB[KKK + l], ez = qkz - bufB[2 * KKK + l];
            float dq = sqrtf(ex * ex + ey * ey + ez * ez + 1e-12f);
            bool geo = (fabsf(dp - dq) < 0.5f) && rowvalid && (l < neffc) && (l != k);
            unsigned bits = __ballot_sync(0xffffffffu, geo);
            if (lane == 0) smask[k * 16 + ch] = bits;
        }
    }
    __syncthreads();

    float* sm_u = bufA;
    float v = (float)(1.0 / sqrt((double)KKK));
    for (int it = 0; it < 20; it++) {
        sm_u[tid] = sk * v;
        __syncthreads();
        float acc = 0.f;
        const unsigned* mrow = &smask[tid * 16];
        const float4* u4 = (const float4*)sm_u;
#pragma unroll 4
        for (int w = 0; w < 16; w++) {
            unsigned bits = mrow[w];
#pragma unroll
            for (int q = 0; q < 8; q++) {
                float4 u = u4[w * 8 + q];
                if (bits & (1u << (q * 4 + 0))) acc += u.x;
                if (bits & (1u << (q * 4 + 1))) acc += u.y;
                if (bits & (1u << (q * 4 + 2))) acc += u.z;
                if (bits & (1u << (q * 4 + 3))) acc += u.w;
            }
        }
        float wv = sk * acc;
        float ss = wv * wv;
#pragma unroll
        for (int m = 16; m >= 1; m >>= 1) ss += __shfl_xor_sync(0xffffffffu, ss, m);
        if (lane == 0) red[wid] = ss;
        __syncthreads();
        if (wid == 0) {
            float x = (lane < 16) ? red[lane] : 0.f;
#pragma unroll
            for (int m = 8; m >= 1; m >>= 1) x += __shfl_xor_sync(0xffffffffu, x, m);
            if (lane == 0) red[32] = sqrtf(x);
        }
        __syncthreads();
        v = wv / (red[32] + 1e-8f);
    }

    float* sv = bufB;
    __syncthreads();
    sv[tid] = v;
    __syncthreads();
    for (int size = 2; size <= KKK; size <<= 1)
        for (int stride = size >> 1; stride > 0; stride >>= 1) {
            int jj = tid ^ stride;
            if (jj > tid) {
                float x1 = sv[tid], x2 = sv[jj];
                bool g  = (x1 < x2);
                bool dd = ((tid & size) == 0);
                if (g == dd) { sv[tid] = x2; sv[jj] = x1; }
            }
            __syncthreads();
        }

    float hacc = b1[tid];
    {
        const float4* sv4 = (const float4*)sv;
#pragma unroll 4
        for (int l4 = 0; l4 < 128; l4++) {
            float4 e = sv4[l4];
            hacc += e.x * W1[(size_t)(l4 * 4 + 0) * KKK + tid];
            hacc += e.y * W1[(size_t)(l4 * 4 + 1) * KKK + tid];
            hacc += e.z * W1[(size_t)(l4 * 4 + 2) * KKK + tid];
            hacc += e.w * W1[(size_t)(l4 * 4 + 3) * KKK + tid];
        }
    }
    float h = fmaxf(hacc, 0.f);
    float contrib = h * W2[tid];
#pragma unroll
    for (int m = 16; m >= 1; m >>= 1) contrib += __shfl_xor_sync(0xffffffffu, contrib, m);
    if (lane == 0) red[wid] = contrib;
    __syncthreads();
    if (tid == 0) {
        float x = 0.f;
        for (int w = 0; w < 16; w++) x += red[w];
        float score = 1.f / (1.f + expf(-(x + b2[0])));
        out[p] = score;
        if (NPAIR + p < out_size) out[NPAIR + p] = (n == 0) ? 1.f : 0.f;
    }
}

extern "C" void kernel_launch(void* const* d_in, const int* in_sizes, int n_in,
                              void* d_out, int out_size) {
    const float* rt    = (const float*)d_in[0];
    const float* cents = (const float*)d_in[1];
    const float* attn  = (const float*)d_in[2];
    const float* sns   = (const float*)d_in[3];
    const int*   nrt   = (const int*)d_in[4];
    const int*   anc   = (const int*)d_in[5];
    const int*   pos   = (const int*)d_in[6];
    const int*   neg   = (const int*)d_in[7];
    const float* Win   = (const float*)d_in[8];
    const float* bin   = (const float*)d_in[9];
    const float* W1    = (const float*)d_in[10];
    const float* b1    = (const float*)d_in[11];
    const float* W2    = (const float*)d_in[12];
    const float* b2    = (const float*)d_in[13];
    float* out = (float*)d_out;

    cudaFuncSetAttribute(gemmG_mma_kernel, cudaFuncAttributeMaxDynamicSharedMemorySize, GDYN_SMEM);

    topk_kernel<<<BB, 1024>>>(attn, nrt, cents, sns);
    gemmF_kernel<<<dim3(CCC / 128, BB * KKK / 128), 256>>>(rt, Win, bin);
    gemmG_mma_kernel<<<dim3(NPAIR, 4, 4), 256, GDYN_SMEM>>>(anc, pos, neg);
    refine_kernel<<<dim3(NPAIR, 16), 256>>>(anc, pos, neg);
    pair_kernel<<<NPAIR, 512>>>(anc, pos, neg, W1, b1, W2, b2, out, out_size);
}

// round 10
// speedup vs baseline: 1.6915x; 1.0036x over previous
#include <cuda_runtime.h>
#include <cuda_bf16.h>
#include <cuda_fp16.h>
#include <cstdint>
#include <math.h>

#define BB 64
#define NNN 1024
#define CCC 256
#define KKK 512
#define NPAIR 128

__device__ float g_F[(size_t)BB * KKK * CCC];
__device__ __nv_bfloat16 g_Fh[(size_t)BB * KKK * CCC];
__device__ __nv_bfloat16 g_Fl[(size_t)BB * KKK * CCC];
__device__ __half g_D[(size_t)NPAIR * KKK * KKK];   // fp16 keys
__device__ float g_norm2[BB * KKK];
__device__ float g_cx[BB * KKK];
__device__ float g_cy[BB * KKK];
__device__ float g_cz[BB * KKK];
__device__ int   g_idx[BB * KKK];
__device__ int   g_neff[BB];
__device__ int   g_corr[NPAIR * KKK];
__device__ float g_s[NPAIR * KKK];

__device__ __forceinline__ uint32_t smem_u32(const void* p) {
    uint32_t a;
    asm("{ .reg .u64 t; cvta.to.shared.u64 t, %1; cvt.u32.u64 %0, t; }" : "=r"(a) : "l"(p));
    return a;
}
__device__ __forceinline__ void cp_async16(uint32_t saddr, const void* g) {
    asm volatile("cp.async.cg.shared.global [%0], [%1], 16;" :: "r"(saddr), "l"(g));
}
#define CP_COMMIT() asm volatile("cp.async.commit_group;" ::: "memory")

#define LDSM_X4(R0, R1, R2, R3, ADDR) \
    asm volatile("ldmatrix.sync.aligned.m8n8.x4.shared.b16 {%0,%1,%2,%3}, [%4];" \
        : "=r"(R0), "=r"(R1), "=r"(R2), "=r"(R3) : "r"(ADDR))

#define MMA_BF16(D, A, B0, B1) \
    asm volatile("mma.sync.aligned.m16n8k16.row.col.f32.bf16.bf16.f32 " \
        "{%0,%1,%2,%3}, {%4,%5,%6,%7}, {%8,%9}, {%0,%1,%2,%3};" \
        : "+f"((D)[0]), "+f"((D)[1]), "+f"((D)[2]), "+f"((D)[3]) \
        : "r"((A)[0]), "r"((A)[1]), "r"((A)[2]), "r"((A)[3]), "r"(B0), "r"(B1))

// ---- kernel 0: per-batch top-K via bitonic sort on (-attn, idx); zeroes g_norm2 ----
__global__ __launch_bounds__(1024) void topk_kernel(
    const float* __restrict__ attn, const int* __restrict__ num_rt,
    const float* __restrict__ cents, const float* __restrict__ sns)
{
    __shared__ float skey[NNN];
    __shared__ int   sidx[NNN];
    const int b = blockIdx.x, tid = threadIdx.x;
    const int nr = num_rt[b];
    if (tid < KKK) g_norm2[b * KKK + tid] = 0.f;
    skey[tid] = (tid < nr) ? attn[b * NNN + tid] : -1000000000.0f;
    sidx[tid] = tid;
    __syncthreads();
    for (int size = 2; size <= NNN; size <<= 1)
        for (int stride = size >> 1; stride > 0; stride >>= 1) {
            int j = tid ^ stride;
            if (j > tid) {
                float k1 = skey[tid], k2 = skey[j];
                int   i1 = sidx[tid], i2 = sidx[j];
                bool g  = (k1 < k2) || (k1 == k2 && i1 > i2);
                bool dd = ((tid & size) == 0);
                if (g == dd) { skey[tid] = k2; skey[j] = k1; sidx[tid] = i2; sidx[j] = i1; }
            }
            __syncthreads();
        }
    if (tid < KKK) {
        int i = sidx[tid];
        g_idx[b * KKK + tid] = i;
        float sc = sns[b * 4 + 3];
        float cx = cents[(b * NNN + i) * 3 + 0];
        float cy = cents[(b * NNN + i) * 3 + 1];
        float cz = cents[(b * NNN + i) * 3 + 2];
        if (i < nr) {
            cx = cx * sc + sns[b * 4 + 0];
            cy = cy * sc + sns[b * 4 + 1];
            cz = cz * sc + sns[b * 4 + 2];
        }
        g_cx[b * KKK + tid] = cx;
        g_cy[b * KKK + tid] = cy;
        g_cz[b * KKK + tid] = cz;
    }
    if (tid == 0) g_neff[b] = (nr < KKK) ? nr : KKK;
}

// ---- kernel 1: F = gather(rt) @ W_in + b_in (fp32 SIMT, reg-prefetch pipeline) ----
__global__ __launch_bounds__(256) void gemmF_kernel(
    const float* __restrict__ rt, const float* __restrict__ Win,
    const float* __restrict__ bin)
{
    __shared__ float As[16][128];
    __shared__ float Bs[16][128];
    const int tid = threadIdx.x;
    const int r0 = blockIdx.y * 128;
    const int c0 = blockIdx.x * 128;
    const int tx = tid & 15, ty = tid >> 4;
    const int lrow = tid >> 1, lc = (tid & 1) * 4;
    const int grow = r0 + lrow;
    const float* arow = rt + ((size_t)(grow >> 9) * NNN + g_idx[grow]) * CCC;
    const int q0 = tid, q1 = tid + 256;
    const float* wp0 = Win + (size_t)(q0 >> 5) * CCC + c0 + (q0 & 31) * 4;
    const float* wp1 = Win + (size_t)(q1 >> 5) * CCC + c0 + (q1 & 31) * 4;

    float acc[8][8];
#pragma unroll
    for (int i = 0; i < 8; i++)
#pragma unroll
        for (int j = 0; j < 8; j++) acc[i][j] = 0.f;

    // prefetch tile 0
    float4 a0 = *(const float4*)(arow + lc);
    float4 a1 = *(const float4*)(arow + lc + 8);
    float4 b0 = *(const float4*)(wp0);
    float4 b1 = *(const float4*)(wp1);

    for (int cN = 0; cN < CCC; cN += 16) {
        __syncthreads();
        As[lc + 0][lrow] = a0.x; As[lc + 1][lrow] = a0.y;
        As[lc + 2][lrow] = a0.z; As[lc + 3][lrow] = a0.w;
        As[lc + 8][lrow] = a1.x; As[lc + 9][lrow] = a1.y;
        As[lc +10][lrow] = a1.z; As[lc +11][lrow] = a1.w;
        *(float4*)&Bs[q0 >> 5][(q0 & 31) * 4] = b0;
        *(float4*)&Bs[q1 >> 5][(q1 & 31) * 4] = b1;
        __syncthreads();
        if (cN + 16 < CCC) {
            a0 = *(const float4*)(arow + cN + 16 + lc);
            a1 = *(const float4*)(arow + cN + 16 + lc + 8);
            b0 = *(const float4*)(wp0 + (size_t)(cN + 16) * CCC);
            b1 = *(const float4*)(wp1 + (size_t)(cN + 16) * CCC);
        }
#pragma unroll
        for (int kk = 0; kk < 16; kk++) {
            float ra[8], rb[8];
            *(float4*)&ra[0] = *(const float4*)&As[kk][ty * 8];
            *(float4*)&ra[4] = *(const float4*)&As[kk][ty * 8 + 4];
            *(float4*)&rb[0] = *(const float4*)&Bs[kk][tx * 8];
            *(float4*)&rb[4] = *(const float4*)&Bs[kk][tx * 8 + 4];
#pragma unroll
            for (int i = 0; i < 8; i++)
#pragma unroll
                for (int j = 0; j < 8; j++) acc[i][j] += ra[i] * rb[j];
        }
    }
#pragma unroll
    for (int i = 0; i < 8; i++) {
        size_t off = (size_t)(r0 + ty * 8 + i) * CCC + c0 + tx * 8;
        float* dst = g_F + off;
        __nv_bfloat16 hi8[8], lo8[8];
        float ps = 0.f;
#pragma unroll
        for (int j = 0; j < 8; j++) {
            float v = acc[i][j] + bin[c0 + tx * 8 + j];
            dst[j] = v;
            ps += v * v;
            __nv_bfloat16 h = __float2bfloat16(v);
            hi8[j] = h;
            lo8[j] = __float2bfloat16(v - __bfloat162float(h));
        }
        *(uint4*)(g_Fh + off) = *(const uint4*)hi8;
        *(uint4*)(g_Fl + off) = *(const uint4*)lo8;
#pragma unroll
        for (int m = 1; m <= 8; m <<= 1) ps += __shfl_xor_sync(0xffffffffu, ps, m);
        if (tx == 0) atomicAdd(&g_norm2[r0 + ty * 8 + i], ps);
    }
}

// ---- kernel 2: mma.sync 2-pass bf16-split GEMM, 3-stage cp.async, fp16-key epilogue ----
#define LDA 40
#define STG_B (128 * LDA)
#define GDYN_SMEM (3 * STG_B * 2 * 2 + 512)
__global__ __launch_bounds__(256, 2) void gemmG_mma_kernel(
    const int* __restrict__ anc, const int* __restrict__ pos,
    const int* __restrict__ neg)
{
    extern __shared__ char smem[];
    __nv_bfloat16* sA = (__nv_bfloat16*)smem;
    __nv_bfloat16* sB = sA + 3 * STG_B;
    float* snorm = (float*)(sB + 3 * STG_B);

    const int tid = threadIdx.x, lane = tid & 31, wid = tid >> 5;
    const int p = blockIdx.x, mtile = blockIdx.y, ntile = blockIdx.z;
    const int t = p >> 1;
    const int a = anc[t];
    const int c = (p & 1) ? neg[t] : pos[t];

    if (tid < 128) snorm[tid] = g_norm2[c * KKK + ntile * 128 + tid];

    const int m_base = (wid >> 1) * 32;
    const int n_base = (wid & 1) * 64;

    float acc[2][8][4];
#pragma unroll
    for (int mi = 0; mi < 2; mi++)
#pragma unroll
        for (int n8 = 0; n8 < 8; n8++)
#pragma unroll
            for (int r = 0; r < 4; r++) acc[mi][n8][r] = 0.f;

    const int ld_row = tid >> 2, ld_q = (tid & 3) * 8;
    const __nv_bfloat16* gAhi = g_Fh + (size_t)(a * KKK + mtile * 128) * CCC;
    const __nv_bfloat16* gAlo = g_Fl + (size_t)(a * KKK + mtile * 128) * CCC;
    const __nv_bfloat16* gB   = g_Fh + (size_t)(c * KKK + ntile * 128) * CCC;
    const size_t go1 = (size_t)ld_row * CCC + ld_q;
    const size_t go2 = (size_t)(ld_row + 64) * CCC + ld_q;
    const uint32_t so1 = (uint32_t)((ld_row * LDA + ld_q) * 2);
    const uint32_t so2 = (uint32_t)(((ld_row + 64) * LDA + ld_q) * 2);
    const uint32_t sAu = smem_u32(sA), sBu = smem_u32(sB);

#define ISSUE(KC, ST) do { \
        const __nv_bfloat16* Asrc = ((KC) >= 8 ? gAlo : gAhi) + ((KC) & 7) * 32; \
        const __nv_bfloat16* Bsrc = gB + ((KC) & 7) * 32; \
        uint32_t dA = sAu + (uint32_t)(ST) * (STG_B * 2); \
        uint32_t dB = sBu + (uint32_t)(ST) * (STG_B * 2); \
        cp_async16(dA + so1, Asrc + go1); \
        cp_async16(dB + so1, Bsrc + go1); \
        cp_async16(dA + so2, Asrc + go2); \
        cp_async16(dB + so2, Bsrc + go2); \
        CP_COMMIT(); \
    } while (0)

    ISSUE(0, 0);
    ISSUE(1, 1);
    for (int kc = 0; kc < 16; kc++) {
        const int buf = kc % 3;
        if (kc + 2 < 16) {
            ISSUE(kc + 2, (kc + 2) % 3);
            asm volatile("cp.async.wait_group 2;" ::: "memory");
        } else if (kc + 1 < 16) {
            asm volatile("cp.async.wait_group 1;" ::: "memory");
        } else {
            asm volatile("cp.async.wait_group 0;" ::: "memory");
        }
        __syncthreads();
        const uint32_t sa = sAu + (uint32_t)buf * (STG_B * 2);
        const uint32_t sb = sBu + (uint32_t)buf * (STG_B * 2);
#pragma unroll
        for (int ks = 0; ks < 2; ks++) {
            const int k0 = ks * 16;
            uint32_t af[2][4];
#pragma unroll
            for (int mi = 0; mi < 2; mi++) {
                uint32_t addr = sa + (uint32_t)(((m_base + mi * 16 + (lane & 15)) * LDA + k0 + (lane >> 4) * 8) << 1);
                LDSM_X4(af[mi][0], af[mi][1], af[mi][2], af[mi][3], addr);
            }
            uint32_t bfr[4][4];
#pragma unroll
            for (int nj = 0; nj < 4; nj++) {
                uint32_t addr = sb + (uint32_t)(((n_base + nj * 16 + (lane & 7) + ((lane >> 4) << 3)) * LDA + k0 + ((lane >> 3) & 1) * 8) << 1);
                LDSM_X4(bfr[nj][0], bfr[nj][1], bfr[nj][2], bfr[nj][3], addr);
            }
#pragma unroll
            for (int mi = 0; mi < 2; mi++)
#pragma unroll
                for (int n8 = 0; n8 < 8; n8++)
                    MMA_BF16(acc[mi][n8], af[mi], bfr[n8 >> 1][(n8 & 1) * 2], bfr[n8 >> 1][(n8 & 1) * 2 + 1]);
        }
        __syncthreads();
    }
#undef ISSUE

#pragma unroll
    for (int mi = 0; mi < 2; mi++)
#pragma unroll
        for (int half = 0; half < 2; half++) {
            int grow = mtile * 128 + m_base + mi * 16 + half * 8 + (lane >> 2);
            int lc0 = n_base + (lane & 3) * 2;
            __half* dst = g_D + ((size_t)p * KKK + grow) * KKK + ntile * 128 + lc0;
#pragma unroll
            for (int n8 = 0; n8 < 8; n8++) {
                float k0v = snorm[lc0 + n8 * 8]     - 2.f * acc[mi][n8][half * 2 + 0];
                float k1v = snorm[lc0 + n8 * 8 + 1] - 2.f * acc[mi][n8][half * 2 + 1];
                *(__half2*)(dst + n8 * 8) = __floats2half2_rn(k0v, k1v);
            }
        }
}

// ---- kernel 2b: exact argmin refinement from fp16 keys (vectorized loads) ----
#define DELTA 3.0f
__global__ __launch_bounds__(256) void refine_kernel(
    const int* __restrict__ anc, const int* __restrict__ pos,
    const int* __restrict__ neg)
{
    __shared__ float snorm[KKK];
    const int p = blockIdx.x, tid = threadIdx.x;
    const int t = p >> 1;
    const int a = anc[t];
    const int c = (p & 1) ? neg[t] : pos[t];
    const int wid = tid >> 5, lane = tid & 31;
    for (int i = tid; i < KKK; i += 256) snorm[i] = g_norm2[c * KKK + i];
    __syncthreads();

    for (int rr = 0; rr < 4; rr++) {
        const int r = blockIdx.y * 32 + rr * 8 + wid;
        const uint4* drow = (const uint4*)(g_D + ((size_t)p * KKK + r) * KKK);
        // lane owns 16 contiguous keys: cols [lane*16, lane*16+16)
        uint4 v0 = drow[lane * 2];
        uint4 v1 = drow[lane * 2 + 1];
        float key[16];
        {
            const uint32_t w[8] = {v0.x, v0.y, v0.z, v0.w, v1.x, v1.y, v1.z, v1.w};
#pragma unroll
            for (int q = 0; q < 8; q++) {
                __half2 h2 = *(const __half2*)&w[q];
                float2 f2 = __half22float2(h2);
                key[q * 2 + 0] = f2.x;
                key[q * 2 + 1] = f2.y;
            }
        }
        float bk = 3.4e38f;
#pragma unroll
        for (int j = 0; j < 16; j++) bk = fminf(bk, key[j]);
#pragma unroll
        for (int m = 16; m >= 1; m >>= 1) bk = fminf(bk, __shfl_xor_sync(0xffffffffu, bk, m));
        const float thr = bk + DELTA;

        unsigned mymask = 0;
#pragma unroll
        for (int j = 0; j < 16; j++)
            if (key[j] <= thr) mymask |= (1u << j);

        float bestk = 3.4e38f; int bestc = 0; float bestd = 0.f;
        const float* fa = g_F + ((size_t)a * KKK + r) * CCC;
        unsigned active = __ballot_sync(0xffffffffu, mymask != 0);
        while (active) {
            int src = __ffs(active) - 1; active &= active - 1;
            unsigned mk = __shfl_sync(0xffffffffu, mymask, src);
            while (mk) {
                int j = __ffs(mk) - 1; mk &= mk - 1;
                int col = src * 16 + j;
                const float* fb = g_F + ((size_t)c * KKK + col) * CCC;
                float sd = 0.f;
#pragma unroll
                for (int q = 0; q < 8; q++) sd += fa[lane * 8 + q] * fb[lane * 8 + q];
#pragma unroll
                for (int mm = 16; mm >= 1; mm >>= 1) sd += __shfl_xor_sync(0xffffffffu, sd, mm);
                float ek = snorm[col] - 2.f * sd;
                if (ek < bestk) { bestk = ek; bestc = col; bestd = sd; }
            }
        }
        if (lane == 0) {
            float na = sqrtf(g_norm2[a * KKK + r]);
            float nb = sqrtf(snorm[bestc]);
            g_s[p * KKK + r]    = fmaxf(bestd / (na * nb + 1e-8f), 0.f);
            g_corr[p * KKK + r] = bestc;
        }
    }
}

// ---- kernel 3: geo bitmask + power iteration + sort + MLP ----
__global__ __launch_bounds__(512) void pair_kernel(
    const int* __restrict__ anc, const int* __restrict__ pos,
    const int* __restrict__ neg,
    const float* __restrict__ W1, const float* __restrict__ b1,
    const float* __restrict__ W2, const float* __restrict__ b2,
    float* __restrict__ out, int out_size)
{
    __shared__ unsigned int smask[KKK * 16];
    __shared__ float bufA[KKK * 3];
    __shared__ float bufB[KKK * 3];
    __shared__ float red[33];

    const int p = blockIdx.x, tid = threadIdx.x;
    const int t = p >> 1, n = p & 1;
    const int a = anc[t];
    const int c = n ? neg[t] : pos[t];
    const int neffa = g_neff[a], neffc = g_neff[c];
    const int wid = tid >> 5, lane = tid & 31;

    bufA[tid]           = g_cx[a * KKK + tid];
    bufA[KKK + tid]     = g_cy[a * KKK + tid];
    bufA[2 * KKK + tid] = g_cz[a * KKK + tid];
    {
        int j = g_corr[p * KKK + tid];
        bufB[tid]           = g_cx[c * KKK + j];
        bufB[KKK + tid]     = g_cy[c * KKK + j];
        bufB[2 * KKK + tid] = g_cz[c * KKK + j];
    }
    float sk = g_s[p * KKK + tid];
    __syncthreads();

    for (int kr = 0; kr < 32; kr++) {
        int k = wid * 32 + kr;
        float akx = bufA[k], aky = bufA[KKK + k], akz = bufA[2 * KKK + k];
        float qkx = bufB[k], qky = bufB[KKK + k], qkz = bufB[2 * KKK + k];
        bool rowvalid = (k < neffa);
#pragma unroll 4
        for (int ch = 0; ch < 16; ch++) {
            int l = ch * 32 + lane;
            float dx = akx - bufA[l], dy = aky - bufA[KKK + l], dz = akz - bufA[2 * KKK + l];
            float dp = sqrtf(dx * dx + dy * dy + dz * dz + 1e-12f);
            float ex = qkx - bufB[l], ey = qky - bufB[KKK + l], ez = qkz - bufB[2 * KKK + l];
            float dq = sqrtf(ex * ex + ey * ey + ez * ez + 1e-12f);
            bool geo = (fabsf(dp - dq) < 0.5f) && rowvalid && (l < neffc) && (l != k);
            unsigned bits = __ballot_sync(0xffffffffu, geo);
            if (lane == 0) smask[k * 16 + ch] = bits;
        }
    }
    __syncthreads();

    float* sm_u = bufA;
    float v = (float)(1.0 / sqrt((double)KKK));
    for (int it = 0; it < 20; it++) {
        sm_u[tid] = sk * v;
        __syncthreads();
        float acc = 0.f;
        const unsigned* mrow = &smask[tid * 16];
        const float4* u4 = (const float4*)sm_u;
#pragma unroll 4
        for (int w = 0; w < 16; w++) {
            unsigned bits = mrow[w];
#pragma unroll
            for (int q = 0; q < 8; q++) {
                float4 u = u4[w * 8 + q];
                if (bits & (1u << (q * 4 + 0))) acc += u.x;
                if (bits & (1u << (q * 4 + 1))) acc += u.y;
                if (bits & (1u << (q * 4 + 2))) acc += u.z;
                if (bits & (1u << (q * 4 + 3))) acc += u.w;
            }
        }
        float wv = sk * acc;
        float ss = wv * wv;
#pragma unroll
        for (int m = 16; m >= 1; m >>= 1) ss += __shfl_xor_sync(0xffffffffu, ss, m);
        if (lane == 0) red[wid] = ss;
        __syncthreads();
        if (wid == 0) {
            float x = (lane < 16) ? red[lane] : 0.f;
#pragma unroll
            for (int m = 8; m >= 1; m >>= 1) x += __shfl_xor_sync(0xffffffffu, x, m);
            if (lane == 0) red[32] = sqrtf(x);
        }
        __syncthreads();
        v = wv / (red[32] + 1e-8f);
    }

    float* sv = bufB;
    __syncthreads();
    sv[tid] = v;
    __syncthreads();
    for (int size = 2; size <= KKK; size <<= 1)
        for (int stride = size >> 1; stride > 0; stride >>= 1) {
            int jj = tid ^ stride;
            if (jj > tid) {
                float x1 = sv[tid], x2 = sv[jj];
                bool g  = (x1 < x2);
                bool dd = ((tid & size) == 0);
                if (g == dd) { sv[tid] = x2; sv[jj] = x1; }
            }
            __syncthreads();
        }

    float hacc = b1[tid];
    {
        const float4* sv4 = (const float4*)sv;
#pragma unroll 4
        for (int l4 = 0; l4 < 128; l4++) {
            float4 e = sv4[l4];
            hacc += e.x * W1[(size_t)(l4 * 4 + 0) * KKK + tid];
            hacc += e.y * W1[(size_t)(l4 * 4 + 1) * KKK + tid];
            hacc += e.z * W1[(size_t)(l4 * 4 + 2) * KKK + tid];
            hacc += e.w * W1[(size_t)(l4 * 4 + 3) * KKK + tid];
        }
    }
    float h = fmaxf(hacc, 0.f);
    float contrib = h * W2[tid];
#pragma unroll
    for (int m = 16; m >= 1; m >>= 1) contrib += __shfl_xor_sync(0xffffffffu, contrib, m);
    if (lane == 0) red[wid] = contrib;
    __syncthreads();
    if (tid == 0) {
        float x = 0.f;
        for (int w = 0; w < 16; w++) x += red[w];
        float score = 1.f / (1.f + expf(-(x + b2[0])));
        out[p] = score;
        if (NPAIR + p < out_size) out[NPAIR + p] = (n == 0) ? 1.f : 0.f;
    }
}

extern "C" void kernel_launch(void* const* d_in, const int* in_sizes, int n_in,
                              void* d_out, int out_size) {
    const float* rt    = (const float*)d_in[0];
    const float* cents = (const float*)d_in[1];
    const float* attn  = (const float*)d_in[2];
    const float* sns   = (const float*)d_in[3];
    const int*   nrt   = (const int*)d_in[4];
    const int*   anc   = (const int*)d_in[5];
    const int*   pos   = (const int*)d_in[6];
    const int*   neg   = (const int*)d_in[7];
    const float* Win   = (const float*)d_in[8];
    const float* bin   = (const float*)d_in[9];
    const float* W1    = (const float*)d_in[10];
    const float* b1    = (const float*)d_in[11];
    const float* W2    = (const float*)d_in[12];
    const float* b2    = (const float*)d_in[13];
    float* out = (float*)d_out;

    cudaFuncSetAttribute(gemmG_mma_kernel, cudaFuncAttributeMaxDynamicSharedMemorySize, GDYN_SMEM);

    topk_kernel<<<BB, 1024>>>(attn, nrt, cents, sns);
    gemmF_kernel<<<dim3(CCC / 128, BB * KKK / 128), 256>>>(rt, Win, bin);
    gemmG_mma_kernel<<<dim3(NPAIR, 4, 4), 256, GDYN_SMEM>>>(anc, pos, neg);
    refine_kernel<<<dim3(NPAIR, 16), 256>>>(anc, pos, neg);
    pair_kernel<<<NPAIR, 512>>>(anc, pos, neg, W1, b1, W2, b2, out, out_size);
}